// round 9
// baseline (speedup 1.0000x reference)
#include <cuda_runtime.h>
#include <cuda_fp16.h>
#include <math.h>
#include <stdint.h>

// Problem constants
#define T  8192
#define DM 1024
#define EM 8
#define HM 4096

// Tiling: CTA 128x256, BK=32, 8 warps (2x4), warp tile 64x64
#define BM 128
#define BK 32
#define ASTRH 40     // sA row stride in halves (80B)  -> conflict-free ldmatrix
#define BSTRH 264    // sB row stride in halves (528B) -> conflict-free ldmatrix

#define SA_BYTES (2 * BM * ASTRH * 2)        // 20480
#define SB_BYTES (2 * BK * BSTRH * 2)        // 33792
#define OFF_SB   SA_BYTES
#define OFF_TOK  (SA_BYTES + SB_BYTES)       // 54272
#define OFF_GATE (OFF_TOK + 512)
#define SMEM_BYTES (OFF_GATE + 512 + 256)

// Device scratch
__device__ int    g_count[EM];
__device__ int    g_tok[EM * T];
__device__ float  g_gate[EM * T];
__device__ __half g_xh[T * DM];
__device__ __half g_wgh[EM * DM * HM];
__device__ __half g_wuh[EM * DM * HM];
__device__ __half g_wdh[EM * HM * DM];
__device__ __half g_hh[EM * T * HM];

// ---------------------------------------------------------------------------
// helpers
// ---------------------------------------------------------------------------
__device__ __forceinline__ void mma_f16(float d[4], const uint32_t a[4], const uint32_t b[2]) {
    asm volatile(
        "mma.sync.aligned.m16n8k16.row.col.f32.f16.f16.f32 "
        "{%0,%1,%2,%3}, {%4,%5,%6,%7}, {%8,%9}, {%0,%1,%2,%3};"
        : "+f"(d[0]), "+f"(d[1]), "+f"(d[2]), "+f"(d[3])
        : "r"(a[0]), "r"(a[1]), "r"(a[2]), "r"(a[3]),
          "r"(b[0]), "r"(b[1]));
}

__device__ __forceinline__ void ldsm4(uint32_t& r0, uint32_t& r1, uint32_t& r2, uint32_t& r3,
                                      uint32_t saddr) {
    asm volatile("ldmatrix.sync.aligned.m8n8.x4.shared.b16 {%0,%1,%2,%3}, [%4];"
                 : "=r"(r0), "=r"(r1), "=r"(r2), "=r"(r3) : "r"(saddr));
}
__device__ __forceinline__ void ldsm4t(uint32_t& r0, uint32_t& r1, uint32_t& r2, uint32_t& r3,
                                       uint32_t saddr) {
    asm volatile("ldmatrix.sync.aligned.m8n8.x4.trans.shared.b16 {%0,%1,%2,%3}, [%4];"
                 : "=r"(r0), "=r"(r1), "=r"(r2), "=r"(r3) : "r"(saddr));
}

__device__ __forceinline__ void cp16(void* smem_ptr, const void* gptr, bool valid) {
    uint32_t sa = (uint32_t)__cvta_generic_to_shared(smem_ptr);
    int sz = valid ? 16 : 0;
    asm volatile("cp.async.cg.shared.global [%0], [%1], 16, %2;"
                 :: "r"(sa), "l"(gptr), "r"(sz));
}
__device__ __forceinline__ void cp_commit() { asm volatile("cp.async.commit_group;"); }
template <int N>
__device__ __forceinline__ void cp_wait() { asm volatile("cp.async.wait_group %0;" :: "n"(N)); }

// ---------------------------------------------------------------------------
// prep: zero out + convert x to fp16 + zero counters
// ---------------------------------------------------------------------------
__global__ void k_prep(float4* __restrict__ out, const float4* __restrict__ x, int n4) {
    int i = blockIdx.x * blockDim.x + threadIdx.x;
    if (i < n4) {
        out[i] = make_float4(0.f, 0.f, 0.f, 0.f);
        float4 v = x[i];
        ((__half2*)g_xh)[2 * i    ] = __floats2half2_rn(v.x, v.y);
        ((__half2*)g_xh)[2 * i + 1] = __floats2half2_rn(v.z, v.w);
    }
    if (i < EM) g_count[i] = 0;
}

// fused fp32->fp16 conversion of all 3 weight tensors (z selects tensor)
__global__ void k_cvt3(const float4* __restrict__ wg, const float4* __restrict__ wu,
                       const float4* __restrict__ wd, int n4) {
    int i = blockIdx.x * blockDim.x + threadIdx.x;
    if (i >= n4) return;
    const float4* src;
    __half2* dst;
    if (blockIdx.z == 0)      { src = wg; dst = (__half2*)g_wgh; }
    else if (blockIdx.z == 1) { src = wu; dst = (__half2*)g_wuh; }
    else                      { src = wd; dst = (__half2*)g_wdh; }
    float4 v = src[i];
    dst[2 * i    ] = __floats2half2_rn(v.x, v.y);
    dst[2 * i + 1] = __floats2half2_rn(v.z, v.w);
}

// ---------------------------------------------------------------------------
// router: one warp per token (fp32, unchanged)
// ---------------------------------------------------------------------------
__global__ void k_router(const float* __restrict__ x,
                         const float* __restrict__ Wr,
                         const float* __restrict__ br) {
    int t    = blockIdx.x * (blockDim.x >> 5) + (threadIdx.x >> 5);
    int lane = threadIdx.x & 31;
    if (t >= T) return;

    const float* xr = x + (size_t)t * DM;
    float acc[EM];
#pragma unroll
    for (int e = 0; e < EM; e++) acc[e] = 0.0f;

    for (int d = lane; d < DM; d += 32) {
        float xv = xr[d];
        const float4 w0 = *(const float4*)(Wr + (size_t)d * EM);
        const float4 w1 = *(const float4*)(Wr + (size_t)d * EM + 4);
        acc[0] += xv * w0.x; acc[1] += xv * w0.y;
        acc[2] += xv * w0.z; acc[3] += xv * w0.w;
        acc[4] += xv * w1.x; acc[5] += xv * w1.y;
        acc[6] += xv * w1.z; acc[7] += xv * w1.w;
    }
#pragma unroll
    for (int e = 0; e < EM; e++) {
#pragma unroll
        for (int o = 16; o > 0; o >>= 1)
            acc[e] += __shfl_xor_sync(0xffffffffu, acc[e], o);
    }

    if (lane == 0) {
        float v[EM];
#pragma unroll
        for (int e = 0; e < EM; e++) v[e] = acc[e] + br[e];

        int b0 = 0; float m0 = v[0];
#pragma unroll
        for (int e = 1; e < EM; e++) if (v[e] > m0) { m0 = v[e]; b0 = e; }
        int b1 = -1; float m1 = -3.4e38f;
#pragma unroll
        for (int e = 0; e < EM; e++) {
            if (e == b0) continue;
            if (v[e] > m1) { m1 = v[e]; b1 = e; }
        }
        float p0 = 1.0f / (1.0f + expf(m1 - m0));
        float p1 = 1.0f - p0;

        int pos = atomicAdd(&g_count[b0], 1);
        g_tok[b0 * T + pos] = t;  g_gate[b0 * T + pos] = p0;
        pos = atomicAdd(&g_count[b1], 1);
        g_tok[b1 * T + pos] = t;  g_gate[b1 * T + pos] = p1;
    }
}

// ---------------------------------------------------------------------------
// fp16 gemm step: one BK=32 k-tile = 2 kk-steps of k16, warp tile 64x64
// ---------------------------------------------------------------------------
__device__ __forceinline__ void gemm_step_f16(
    uint32_t sa_base, uint32_t sb_base,
    int wm, int wn, int lane, float cc[4][8][4]) {

    const int mid = lane >> 3, mr = lane & 7;
    const int arow  = (mid & 1) * 8 + mr;
    const int akoff = (mid >> 1) * 8;
    const int bkrow = (mid & 1) * 8 + mr;
    const int bcoff = (mid >> 1) * 8;

#pragma unroll
    for (int kk = 0; kk < BK; kk += 16) {
        uint32_t af[4][4];
#pragma unroll
        for (int im = 0; im < 4; im++) {
            uint32_t addr = sa_base + ((wm + im * 16 + arow) * ASTRH + kk + akoff) * 2;
            ldsm4(af[im][0], af[im][1], af[im][2], af[im][3], addr);
        }
        uint32_t bf[8][2];
#pragma unroll
        for (int inp = 0; inp < 4; inp++) {
            uint32_t addr = sb_base + ((kk + bkrow) * BSTRH + wn + inp * 16 + bcoff) * 2;
            uint32_t r0, r1, r2, r3;
            ldsm4t(r0, r1, r2, r3, addr);
            bf[2 * inp    ][0] = r0; bf[2 * inp    ][1] = r1;
            bf[2 * inp + 1][0] = r2; bf[2 * inp + 1][1] = r3;
        }
#pragma unroll
        for (int in = 0; in < 8; in++)
#pragma unroll
            for (int im = 0; im < 4; im++)
                mma_f16(cc[im][in], af[im], bf[in]);
    }
}

// ---------------------------------------------------------------------------
// phase 1: h = silu(x@Wg+bg) * (x@Wu+bu)
// B tile: 256 smem cols = 32 n8-blocks, even -> Wg, odd -> Wu (same 128 h cols)
// grid: (T/BM, HM/128, EM), 256 threads, 2-stage cp.async
// ---------------------------------------------------------------------------
__global__ __launch_bounds__(256) void k_ffn1(
    const float* __restrict__ bg, const float* __restrict__ bu) {

    const int e      = blockIdx.z;
    const int cnt    = g_count[e];
    const int m_base = blockIdx.x * BM;
    if (m_base >= cnt) return;
    const int n_base = blockIdx.y * 128;   // logical H columns

    extern __shared__ __align__(16) char smem[];
    __half* sA  = (__half*)smem;
    __half* sB  = (__half*)(smem + OFF_SB);
    int*   sTok = (int*)(smem + OFF_TOK);

    const int tid  = threadIdx.x;
    const int warp = tid >> 5, lane = tid & 31;
    const int g    = lane >> 2, tq  = lane & 3;
    const int wm   = (warp & 1) * 64;
    const int wn   = (warp >> 1) * 64;

    if (tid < BM) {
        int r = m_base + tid;
        sTok[tid] = (r < cnt) ? g_tok[e * T + r] : 0;
    }
    __syncthreads();

    float cc[4][8][4];
#pragma unroll
    for (int a = 0; a < 4; a++)
#pragma unroll
        for (int b = 0; b < 8; b++)
#pragma unroll
            for (int c = 0; c < 4; c++) cc[a][b][c] = 0.0f;

    const __half* wg = g_wgh + (size_t)e * DM * HM + n_base;
    const __half* wu = g_wuh + (size_t)e * DM * HM + n_base;

    auto load_tiles = [&](int st, int k0) {
#pragma unroll
        for (int j = 0; j < 2; j++) {          // A: 128 rows x 32 halves
            int idx = tid + j * 256;
            int row = idx >> 2;
            int c8  = (idx & 3) << 3;
            cp16(&sA[(size_t)st * BM * ASTRH + row * ASTRH + c8],
                 g_xh + (size_t)sTok[row] * DM + k0 + c8, true);
        }
#pragma unroll
        for (int j = 0; j < 4; j++) {          // B: 32 rows x 256 halves (32 n8-chunks)
            int idx = tid + j * 256;
            int kr  = idx >> 5;
            int q   = idx & 31;                // even=Wg, odd=Wu
            const __half* src = (q & 1) ? wu : wg;
            cp16(&sB[(size_t)st * BK * BSTRH + kr * BSTRH + (q << 3)],
                 src + (size_t)(k0 + kr) * HM + ((q >> 1) << 3), true);
        }
        cp_commit();
    };

    uint32_t sa0 = (uint32_t)__cvta_generic_to_shared(sA);
    uint32_t sb0 = (uint32_t)__cvta_generic_to_shared(sB);
    const uint32_t saSz = BM * ASTRH * 2, sbSz = BK * BSTRH * 2;

    load_tiles(0, 0);
    const int KT = DM / BK;   // 32
    for (int kt = 0; kt < KT; kt++) {
        int cur = kt & 1;
        if (kt + 1 < KT) { load_tiles(cur ^ 1, (kt + 1) * BK); cp_wait<1>(); }
        else             { cp_wait<0>(); }
        __syncthreads();
        gemm_step_f16(sa0 + cur * saSz, sb0 + cur * sbSz, wm, wn, lane, cc);
        __syncthreads();
    }

    // epilogue: in=2j -> gate, in=2j+1 -> up (same logical cols), register silu
    const float* bge = bg + (size_t)e * HM;
    const float* bue = bu + (size_t)e * HM;
    __half* hb = g_hh + (size_t)e * T * HM;
#pragma unroll
    for (int im = 0; im < 4; im++) {
        int r0 = m_base + wm + im * 16 + g;
#pragma unroll
        for (int j = 0; j < 4; j++) {
            int c0 = n_base + ((wn >> 4) + j) * 8 + 2 * tq;
            float bg0 = bge[c0], bg1 = bge[c0 + 1];
            float bu0 = bue[c0], bu1 = bue[c0 + 1];
            if (r0 < cnt) {
                float gv0 = cc[im][2 * j][0] + bg0, gv1 = cc[im][2 * j][1] + bg1;
                float uv0 = cc[im][2 * j + 1][0] + bu0, uv1 = cc[im][2 * j + 1][1] + bu1;
                *(__half2*)(hb + (size_t)r0 * HM + c0) = __floats2half2_rn(
                    gv0 / (1.0f + expf(-gv0)) * uv0,
                    gv1 / (1.0f + expf(-gv1)) * uv1);
            }
            if (r0 + 8 < cnt) {
                float gv0 = cc[im][2 * j][2] + bg0, gv1 = cc[im][2 * j][3] + bg1;
                float uv0 = cc[im][2 * j + 1][2] + bu0, uv1 = cc[im][2 * j + 1][3] + bu1;
                *(__half2*)(hb + (size_t)(r0 + 8) * HM + c0) = __floats2half2_rn(
                    gv0 / (1.0f + expf(-gv0)) * uv0,
                    gv1 / (1.0f + expf(-gv1)) * uv1);
            }
        }
    }
}

// ---------------------------------------------------------------------------
// phase 2: out[tok] += gate * (h @ Wd + bd)
// grid: (T/BM, DM/256, EM), 256 threads, 2-stage cp.async
// ---------------------------------------------------------------------------
__global__ __launch_bounds__(256) void k_ffn2(
    const float* __restrict__ bd, float* __restrict__ out) {

    const int e      = blockIdx.z;
    const int cnt    = g_count[e];
    const int m_base = blockIdx.x * BM;
    if (m_base >= cnt) return;
    const int n_base = blockIdx.y * 256;

    extern __shared__ __align__(16) char smem[];
    __half* sA   = (__half*)smem;
    __half* sB   = (__half*)(smem + OFF_SB);
    int*   sTok  = (int*)(smem + OFF_TOK);
    float* sGate = (float*)(smem + OFF_GATE);

    const int tid  = threadIdx.x;
    const int warp = tid >> 5, lane = tid & 31;
    const int g    = lane >> 2, tq  = lane & 3;
    const int wm   = (warp & 1) * 64;
    const int wn   = (warp >> 1) * 64;

    if (tid < BM) {
        int r = m_base + tid;
        sTok[tid]  = (r < cnt) ? g_tok[e * T + r]  : 0;
        sGate[tid] = (r < cnt) ? g_gate[e * T + r] : 0.0f;
    }

    float cc[4][8][4];
#pragma unroll
    for (int a = 0; a < 4; a++)
#pragma unroll
        for (int b = 0; b < 8; b++)
#pragma unroll
            for (int c = 0; c < 4; c++) cc[a][b][c] = 0.0f;

    const __half* hb = g_hh + (size_t)e * T * HM;
    const __half* wd = g_wdh + (size_t)e * HM * DM + n_base;

    auto load_tiles = [&](int st, int k0) {
#pragma unroll
        for (int j = 0; j < 2; j++) {          // A: 128 slot rows x 32 halves (zfill)
            int idx = tid + j * 256;
            int row = idx >> 2;
            int c8  = (idx & 3) << 3;
            bool v  = (m_base + row) < cnt;
            cp16(&sA[(size_t)st * BM * ASTRH + row * ASTRH + c8],
                 hb + (size_t)(m_base + row) * HM + k0 + c8, v);
        }
#pragma unroll
        for (int j = 0; j < 4; j++) {          // B: 32 rows x 256 halves
            int idx = tid + j * 256;
            int kr  = idx >> 5;
            int c8  = (idx & 31) << 3;
            cp16(&sB[(size_t)st * BK * BSTRH + kr * BSTRH + c8],
                 wd + (size_t)(k0 + kr) * DM + c8, true);
        }
        cp_commit();
    };

    uint32_t sa0 = (uint32_t)__cvta_generic_to_shared(sA);
    uint32_t sb0 = (uint32_t)__cvta_generic_to_shared(sB);
    const uint32_t saSz = BM * ASTRH * 2, sbSz = BK * BSTRH * 2;

    load_tiles(0, 0);
    const int KT = HM / BK;   // 128
    for (int kt = 0; kt < KT; kt++) {
        int cur = kt & 1;
        if (kt + 1 < KT) { load_tiles(cur ^ 1, (kt + 1) * BK); cp_wait<1>(); }
        else             { cp_wait<0>(); }
        __syncthreads();
        gemm_step_f16(sa0 + cur * saSz, sb0 + cur * sbSz, wm, wn, lane, cc);
        __syncthreads();
    }

    // epilogue: gate-weighted scatter atomicAdd
    const float* bde = bd + (size_t)e * DM;
#pragma unroll
    for (int im = 0; im < 4; im++) {
        int rl = wm + im * 16 + g;
        int rg = m_base + rl;
#pragma unroll
        for (int in = 0; in < 8; in++) {
            int n = n_base + wn + in * 8 + tq * 2;
            float b0 = bde[n], b1 = bde[n + 1];
            if (rg < cnt) {
                int   t  = sTok[rl];
                float gt = sGate[rl];
                atomicAdd(&out[(size_t)t * DM + n    ], gt * (cc[im][in][0] + b0));
                atomicAdd(&out[(size_t)t * DM + n + 1], gt * (cc[im][in][1] + b1));
            }
            if (rg + 8 < cnt) {
                int   t  = sTok[rl + 8];
                float gt = sGate[rl + 8];
                atomicAdd(&out[(size_t)t * DM + n    ], gt * (cc[im][in][2] + b0));
                atomicAdd(&out[(size_t)t * DM + n + 1], gt * (cc[im][in][3] + b1));
            }
        }
    }
}

// ---------------------------------------------------------------------------
extern "C" void kernel_launch(void* const* d_in, const int* in_sizes, int n_in,
                              void* d_out, int out_size) {
    const float* x  = (const float*)d_in[0];
    const float* Wr = (const float*)d_in[1];
    const float* br = (const float*)d_in[2];
    const float* Wg = (const float*)d_in[3];
    const float* bg = (const float*)d_in[4];
    const float* Wu = (const float*)d_in[5];
    const float* bu = (const float*)d_in[6];
    const float* Wd = (const float*)d_in[7];
    const float* bd = (const float*)d_in[8];
    float* out = (float*)d_out;

    cudaFuncSetAttribute(k_ffn1, cudaFuncAttributeMaxDynamicSharedMemorySize, SMEM_BYTES);
    cudaFuncSetAttribute(k_ffn2, cudaFuncAttributeMaxDynamicSharedMemorySize, SMEM_BYTES);

    int n4x = T * DM / 4;
    k_prep<<<(n4x + 255) / 256, 256>>>((float4*)out, (const float4*)x, n4x);

    int n4w = EM * DM * HM / 4;
    dim3 gc((n4w + 255) / 256, 1, 3);
    k_cvt3<<<gc, 256>>>((const float4*)Wg, (const float4*)Wu, (const float4*)Wd, n4w);

    k_router<<<T / 8, 256>>>(x, Wr, br);

    dim3 g1(T / BM, HM / 128, EM);
    k_ffn1<<<g1, 256, SMEM_BYTES>>>(bg, bu);

    dim3 g2(T / BM, DM / 256, EM);
    k_ffn2<<<g2, 256, SMEM_BYTES>>>(bd, out);
}

// round 10
// speedup vs baseline: 1.1941x; 1.1941x over previous
#include <cuda_runtime.h>
#include <cuda_fp16.h>
#include <math.h>
#include <stdint.h>

// Problem constants
#define T  8192
#define DM 1024
#define EM 8
#define HM 4096

// Tiling: BM=128, 128 smem cols (fp16), BK=32, 8 warps (2x4), warp tile 64x32
#define BM 128
#define BK 32
#define ASTRH 40     // sA row stride in halves (80B) -> conflict-free ldmatrix
#define BSTRH 136    // sB row stride in halves (272B) -> conflict-free ldmatrix
#define NSTG 3       // pipeline stages, 1 sync per k-tile

#define SA_STG (BM * ASTRH)                 // halves per A stage (10240 B)
#define SB_STG (BK * BSTRH)                 // halves per B stage (8704 B)
#define OFF_SB   (NSTG * SA_STG * 2)
#define OFF_TOK  (OFF_SB + NSTG * SB_STG * 2)
#define OFF_GATE (OFF_TOK + 512)
#define SMEM_BYTES (OFF_GATE + 512 + 256)

// Device scratch
__device__ int    g_count[EM];
__device__ int    g_tok[EM * T];
__device__ float  g_gate[EM * T];
__device__ __half g_xh[T * DM];          // fp16 x
__device__ __half g_wgh[EM * DM * HM];   // fp16 weights
__device__ __half g_wuh[EM * DM * HM];
__device__ __half g_wdh[EM * HM * DM];
__device__ __half g_hh[EM * T * HM];     // fp16 hidden activations

// ---------------------------------------------------------------------------
// helpers
// ---------------------------------------------------------------------------
__device__ __forceinline__ void mma_f16(float d[4], const uint32_t a[4], const uint32_t b[2]) {
    asm volatile(
        "mma.sync.aligned.m16n8k16.row.col.f32.f16.f16.f32 "
        "{%0,%1,%2,%3}, {%4,%5,%6,%7}, {%8,%9}, {%0,%1,%2,%3};"
        : "+f"(d[0]), "+f"(d[1]), "+f"(d[2]), "+f"(d[3])
        : "r"(a[0]), "r"(a[1]), "r"(a[2]), "r"(a[3]),
          "r"(b[0]), "r"(b[1]));
}

__device__ __forceinline__ void ldsm4(uint32_t& r0, uint32_t& r1, uint32_t& r2, uint32_t& r3,
                                      uint32_t saddr) {
    asm volatile("ldmatrix.sync.aligned.m8n8.x4.shared.b16 {%0,%1,%2,%3}, [%4];"
                 : "=r"(r0), "=r"(r1), "=r"(r2), "=r"(r3) : "r"(saddr));
}
__device__ __forceinline__ void ldsm4t(uint32_t& r0, uint32_t& r1, uint32_t& r2, uint32_t& r3,
                                       uint32_t saddr) {
    asm volatile("ldmatrix.sync.aligned.m8n8.x4.trans.shared.b16 {%0,%1,%2,%3}, [%4];"
                 : "=r"(r0), "=r"(r1), "=r"(r2), "=r"(r3) : "r"(saddr));
}

__device__ __forceinline__ void cp16(void* smem_ptr, const void* gptr, bool valid) {
    uint32_t sa = (uint32_t)__cvta_generic_to_shared(smem_ptr);
    int sz = valid ? 16 : 0;
    asm volatile("cp.async.cg.shared.global [%0], [%1], 16, %2;"
                 :: "r"(sa), "l"(gptr), "r"(sz));
}
__device__ __forceinline__ void cp_commit() { asm volatile("cp.async.commit_group;"); }
template <int N>
__device__ __forceinline__ void cp_wait() { asm volatile("cp.async.wait_group %0;" :: "n"(N)); }

// ---------------------------------------------------------------------------
// prep: zero out + convert x to fp16 + zero counters
// ---------------------------------------------------------------------------
__global__ void k_prep(float4* __restrict__ out, const float4* __restrict__ x, int n4) {
    int i = blockIdx.x * blockDim.x + threadIdx.x;
    if (i < n4) {
        out[i] = make_float4(0.f, 0.f, 0.f, 0.f);
        float4 v = x[i];
        ((__half2*)g_xh)[2 * i    ] = __floats2half2_rn(v.x, v.y);
        ((__half2*)g_xh)[2 * i + 1] = __floats2half2_rn(v.z, v.w);
    }
    if (i < EM) g_count[i] = 0;
}

// fused fp32->fp16 conversion of all 3 weight tensors (z selects tensor)
__global__ void k_cvt3(const float4* __restrict__ wg, const float4* __restrict__ wu,
                       const float4* __restrict__ wd, int n4) {
    int i = blockIdx.x * blockDim.x + threadIdx.x;
    if (i >= n4) return;
    const float4* src;
    __half2* dst;
    if (blockIdx.z == 0)      { src = wg; dst = (__half2*)g_wgh; }
    else if (blockIdx.z == 1) { src = wu; dst = (__half2*)g_wuh; }
    else                      { src = wd; dst = (__half2*)g_wdh; }
    float4 v = src[i];
    dst[2 * i    ] = __floats2half2_rn(v.x, v.y);
    dst[2 * i + 1] = __floats2half2_rn(v.z, v.w);
}

// ---------------------------------------------------------------------------
// router: one warp per token (fp32)
// ---------------------------------------------------------------------------
__global__ void k_router(const float* __restrict__ x,
                         const float* __restrict__ Wr,
                         const float* __restrict__ br) {
    int t    = blockIdx.x * (blockDim.x >> 5) + (threadIdx.x >> 5);
    int lane = threadIdx.x & 31;
    if (t >= T) return;

    const float* xr = x + (size_t)t * DM;
    float acc[EM];
#pragma unroll
    for (int e = 0; e < EM; e++) acc[e] = 0.0f;

    for (int d = lane; d < DM; d += 32) {
        float xv = xr[d];
        const float4 w0 = *(const float4*)(Wr + (size_t)d * EM);
        const float4 w1 = *(const float4*)(Wr + (size_t)d * EM + 4);
        acc[0] += xv * w0.x; acc[1] += xv * w0.y;
        acc[2] += xv * w0.z; acc[3] += xv * w0.w;
        acc[4] += xv * w1.x; acc[5] += xv * w1.y;
        acc[6] += xv * w1.z; acc[7] += xv * w1.w;
    }
#pragma unroll
    for (int e = 0; e < EM; e++) {
#pragma unroll
        for (int o = 16; o > 0; o >>= 1)
            acc[e] += __shfl_xor_sync(0xffffffffu, acc[e], o);
    }

    if (lane == 0) {
        float v[EM];
#pragma unroll
        for (int e = 0; e < EM; e++) v[e] = acc[e] + br[e];

        int b0 = 0; float m0 = v[0];
#pragma unroll
        for (int e = 1; e < EM; e++) if (v[e] > m0) { m0 = v[e]; b0 = e; }
        int b1 = -1; float m1 = -3.4e38f;
#pragma unroll
        for (int e = 0; e < EM; e++) {
            if (e == b0) continue;
            if (v[e] > m1) { m1 = v[e]; b1 = e; }
        }
        float p0 = 1.0f / (1.0f + expf(m1 - m0));
        float p1 = 1.0f - p0;

        int pos = atomicAdd(&g_count[b0], 1);
        g_tok[b0 * T + pos] = t;  g_gate[b0 * T + pos] = p0;
        pos = atomicAdd(&g_count[b1], 1);
        g_tok[b1 * T + pos] = t;  g_gate[b1 * T + pos] = p1;
    }
}

// ---------------------------------------------------------------------------
// fp16 gemm step: one BK=32 k-tile = 2 kk-steps of k16, warp tile 64x32
// ---------------------------------------------------------------------------
__device__ __forceinline__ void gemm_step_f16(
    uint32_t sa_base, uint32_t sb_base,
    int wm, int wn, int lane, float cc[4][4][4]) {

    const int mid = lane >> 3, mr = lane & 7;
    const int arow  = (mid & 1) * 8 + mr;
    const int akoff = (mid >> 1) * 8;
    const int bkrow = (mid & 1) * 8 + mr;
    const int bcoff = (mid >> 1) * 8;

#pragma unroll
    for (int kk = 0; kk < BK; kk += 16) {
        uint32_t af[4][4];
#pragma unroll
        for (int im = 0; im < 4; im++) {
            uint32_t addr = sa_base + ((wm + im * 16 + arow) * ASTRH + kk + akoff) * 2;
            ldsm4(af[im][0], af[im][1], af[im][2], af[im][3], addr);
        }
        uint32_t bf[4][2];
#pragma unroll
        for (int inp = 0; inp < 2; inp++) {
            uint32_t addr = sb_base + ((kk + bkrow) * BSTRH + wn + inp * 16 + bcoff) * 2;
            uint32_t r0, r1, r2, r3;
            ldsm4t(r0, r1, r2, r3, addr);
            bf[2 * inp    ][0] = r0; bf[2 * inp    ][1] = r1;
            bf[2 * inp + 1][0] = r2; bf[2 * inp + 1][1] = r3;
        }
#pragma unroll
        for (int in = 0; in < 4; in++)
#pragma unroll
            for (int im = 0; im < 4; im++)
                mma_f16(cc[im][in], af[im], bf[in]);
    }
}

// ---------------------------------------------------------------------------
// phase 1: h = silu(x@Wg+bg) * (x@Wu+bu), fp16 MMA
// B tile: 128 cols = 16 n8-blocks, even -> Wg, odd -> Wu (same 64 h cols)
// grid: (T/BM, HM/64, EM), 256 threads, 3-stage cp.async, 1 sync/k-tile
// ---------------------------------------------------------------------------
__global__ __launch_bounds__(256) void k_ffn1(
    const float* __restrict__ bg, const float* __restrict__ bu) {

    const int e      = blockIdx.z;
    const int cnt    = g_count[e];
    const int m_base = blockIdx.x * BM;
    if (m_base >= cnt) return;
    const int n_base = blockIdx.y * 64;   // logical H columns

    extern __shared__ __align__(16) char smem[];
    __half* sA  = (__half*)smem;
    __half* sB  = (__half*)(smem + OFF_SB);
    int*   sTok = (int*)(smem + OFF_TOK);

    const int tid  = threadIdx.x;
    const int warp = tid >> 5, lane = tid & 31;
    const int g    = lane >> 2, tq  = lane & 3;
    const int wm   = (warp & 1) * 64;
    const int wn   = (warp >> 1) * 32;

    if (tid < BM) {
        int r = m_base + tid;
        sTok[tid] = (r < cnt) ? g_tok[e * T + r] : 0;
    }
    __syncthreads();

    float cc[4][4][4];
#pragma unroll
    for (int a = 0; a < 4; a++)
#pragma unroll
        for (int b = 0; b < 4; b++)
#pragma unroll
            for (int c = 0; c < 4; c++) cc[a][b][c] = 0.0f;

    const __half* wg = g_wgh + (size_t)e * DM * HM + n_base;
    const __half* wu = g_wuh + (size_t)e * DM * HM + n_base;

    auto load_tiles = [&](int st, int k0) {
#pragma unroll
        for (int j = 0; j < 2; j++) {          // A: 128 rows x 32 halves
            int idx = tid + j * 256;
            int row = idx >> 2;
            int c8  = (idx & 3) << 3;
            cp16(&sA[st * SA_STG + row * ASTRH + c8],
                 g_xh + (size_t)sTok[row] * DM + k0 + c8, true);
        }
#pragma unroll
        for (int j = 0; j < 2; j++) {          // B: 32 rows x 128 halves (16 n8-chunks)
            int idx = tid + j * 256;
            int kr  = idx >> 4;
            int q   = idx & 15;                // even=Wg, odd=Wu
            const __half* src = (q & 1) ? wu : wg;
            cp16(&sB[st * SB_STG + kr * BSTRH + (q << 3)],
                 src + (size_t)(k0 + kr) * HM + ((q >> 1) << 3), true);
        }
        cp_commit();
    };

    uint32_t sa0 = (uint32_t)__cvta_generic_to_shared(sA);
    uint32_t sb0 = (uint32_t)__cvta_generic_to_shared(sB);
    const uint32_t saSz = SA_STG * 2, sbSz = SB_STG * 2;

    load_tiles(0, 0);
    load_tiles(1, BK);
    const int KT = DM / BK;   // 32
    int cur = 0, nxt = 2;
    for (int kt = 0; kt < KT; kt++) {
        if (kt + 2 < KT) cp_wait<1>(); else cp_wait<0>();
        __syncthreads();
        if (kt + 2 < KT) load_tiles(nxt, (kt + 2) * BK);
        gemm_step_f16(sa0 + cur * saSz, sb0 + cur * sbSz, wm, wn, lane, cc);
        cur = (cur == NSTG - 1) ? 0 : cur + 1;
        nxt = (nxt == NSTG - 1) ? 0 : nxt + 1;
    }

    // epilogue: in=2j -> gate, in=2j+1 -> up, same logical cols, register silu
    const float* bge = bg + (size_t)e * HM;
    const float* bue = bu + (size_t)e * HM;
    __half* hb = g_hh + (size_t)e * T * HM;
#pragma unroll
    for (int im = 0; im < 4; im++) {
        int r0 = m_base + wm + im * 16 + g;
#pragma unroll
        for (int j = 0; j < 2; j++) {
            int c0 = n_base + ((wn >> 4) + j) * 8 + 2 * tq;
            float bg0 = bge[c0], bg1 = bge[c0 + 1];
            float bu0 = bue[c0], bu1 = bue[c0 + 1];
            if (r0 < cnt) {
                float gv0 = cc[im][2 * j][0] + bg0, gv1 = cc[im][2 * j][1] + bg1;
                float uv0 = cc[im][2 * j + 1][0] + bu0, uv1 = cc[im][2 * j + 1][1] + bu1;
                *(__half2*)(hb + (size_t)r0 * HM + c0) = __floats2half2_rn(
                    gv0 / (1.0f + expf(-gv0)) * uv0,
                    gv1 / (1.0f + expf(-gv1)) * uv1);
            }
            if (r0 + 8 < cnt) {
                float gv0 = cc[im][2 * j][2] + bg0, gv1 = cc[im][2 * j][3] + bg1;
                float uv0 = cc[im][2 * j + 1][2] + bu0, uv1 = cc[im][2 * j + 1][3] + bu1;
                *(__half2*)(hb + (size_t)(r0 + 8) * HM + c0) = __floats2half2_rn(
                    gv0 / (1.0f + expf(-gv0)) * uv0,
                    gv1 / (1.0f + expf(-gv1)) * uv1);
            }
        }
    }
}

// ---------------------------------------------------------------------------
// phase 2: out[tok] += gate * (h @ Wd + bd), fp16 MMA
// grid: (T/BM, DM/128, EM), 256 threads, 3-stage cp.async, 1 sync/k-tile
// ---------------------------------------------------------------------------
__global__ __launch_bounds__(256) void k_ffn2(
    const float* __restrict__ bd, float* __restrict__ out) {

    const int e      = blockIdx.z;
    const int cnt    = g_count[e];
    const int m_base = blockIdx.x * BM;
    if (m_base >= cnt) return;
    const int n_base = blockIdx.y * 128;

    extern __shared__ __align__(16) char smem[];
    __half* sA   = (__half*)smem;
    __half* sB   = (__half*)(smem + OFF_SB);
    int*   sTok  = (int*)(smem + OFF_TOK);
    float* sGate = (float*)(smem + OFF_GATE);

    const int tid  = threadIdx.x;
    const int warp = tid >> 5, lane = tid & 31;
    const int g    = lane >> 2, tq  = lane & 3;
    const int wm   = (warp & 1) * 64;
    const int wn   = (warp >> 1) * 32;

    if (tid < BM) {
        int r = m_base + tid;
        sTok[tid]  = (r < cnt) ? g_tok[e * T + r]  : 0;
        sGate[tid] = (r < cnt) ? g_gate[e * T + r] : 0.0f;
    }

    float cc[4][4][4];
#pragma unroll
    for (int a = 0; a < 4; a++)
#pragma unroll
        for (int b = 0; b < 4; b++)
#pragma unroll
            for (int c = 0; c < 4; c++) cc[a][b][c] = 0.0f;

    const __half* hb = g_hh + (size_t)e * T * HM;
    const __half* wd = g_wdh + (size_t)e * HM * DM + n_base;

    auto load_tiles = [&](int st, int k0) {
#pragma unroll
        for (int j = 0; j < 2; j++) {          // A: 128 slot rows x 32 halves (zfill)
            int idx = tid + j * 256;
            int row = idx >> 2;
            int c8  = (idx & 3) << 3;
            bool v  = (m_base + row) < cnt;
            cp16(&sA[st * SA_STG + row * ASTRH + c8],
                 hb + (size_t)(m_base + row) * HM + k0 + c8, v);
        }
#pragma unroll
        for (int j = 0; j < 2; j++) {          // B: 32 rows x 128 halves
            int idx = tid + j * 256;
            int kr  = idx >> 4;
            int c8  = (idx & 15) << 3;
            cp16(&sB[st * SB_STG + kr * BSTRH + c8],
                 wd + (size_t)(k0 + kr) * DM + c8, true);
        }
        cp_commit();
    };

    uint32_t sa0 = (uint32_t)__cvta_generic_to_shared(sA);
    uint32_t sb0 = (uint32_t)__cvta_generic_to_shared(sB);
    const uint32_t saSz = SA_STG * 2, sbSz = SB_STG * 2;

    load_tiles(0, 0);
    load_tiles(1, BK);
    const int KT = HM / BK;   // 128
    int cur = 0, nxt = 2;
    for (int kt = 0; kt < KT; kt++) {
        if (kt + 2 < KT) cp_wait<1>(); else cp_wait<0>();
        __syncthreads();
        if (kt + 2 < KT) load_tiles(nxt, (kt + 2) * BK);
        gemm_step_f16(sa0 + cur * saSz, sb0 + cur * sbSz, wm, wn, lane, cc);
        cur = (cur == NSTG - 1) ? 0 : cur + 1;
        nxt = (nxt == NSTG - 1) ? 0 : nxt + 1;
    }

    // epilogue: gate-weighted scatter atomicAdd
    const float* bde = bd + (size_t)e * DM;
#pragma unroll
    for (int im = 0; im < 4; im++) {
        int rl = wm + im * 16 + g;
        int rg = m_base + rl;
#pragma unroll
        for (int in = 0; in < 4; in++) {
            int n = n_base + wn + in * 8 + tq * 2;
            float b0 = bde[n], b1 = bde[n + 1];
            if (rg < cnt) {
                int   t  = sTok[rl];
                float gt = sGate[rl];
                atomicAdd(&out[(size_t)t * DM + n    ], gt * (cc[im][in][0] + b0));
                atomicAdd(&out[(size_t)t * DM + n + 1], gt * (cc[im][in][1] + b1));
            }
            if (rg + 8 < cnt) {
                int   t  = sTok[rl + 8];
                float gt = sGate[rl + 8];
                atomicAdd(&out[(size_t)t * DM + n    ], gt * (cc[im][in][2] + b0));
                atomicAdd(&out[(size_t)t * DM + n + 1], gt * (cc[im][in][3] + b1));
            }
        }
    }
}

// ---------------------------------------------------------------------------
extern "C" void kernel_launch(void* const* d_in, const int* in_sizes, int n_in,
                              void* d_out, int out_size) {
    const float* x  = (const float*)d_in[0];
    const float* Wr = (const float*)d_in[1];
    const float* br = (const float*)d_in[2];
    const float* Wg = (const float*)d_in[3];
    const float* bg = (const float*)d_in[4];
    const float* Wu = (const float*)d_in[5];
    const float* bu = (const float*)d_in[6];
    const float* Wd = (const float*)d_in[7];
    const float* bd = (const float*)d_in[8];
    float* out = (float*)d_out;

    cudaFuncSetAttribute(k_ffn1, cudaFuncAttributeMaxDynamicSharedMemorySize, SMEM_BYTES);
    cudaFuncSetAttribute(k_ffn2, cudaFuncAttributeMaxDynamicSharedMemorySize, SMEM_BYTES);

    int n4x = T * DM / 4;
    k_prep<<<(n4x + 255) / 256, 256>>>((float4*)out, (const float4*)x, n4x);

    int n4w = EM * DM * HM / 4;
    dim3 gc((n4w + 255) / 256, 1, 3);
    k_cvt3<<<gc, 256>>>((const float4*)Wg, (const float4*)Wu, (const float4*)Wd, n4w);

    k_router<<<T / 8, 256>>>(x, Wr, br);

    dim3 g1(T / BM, HM / 64, EM);
    k_ffn1<<<g1, 256, SMEM_BYTES>>>(bg, bu);

    dim3 g2(T / BM, DM / 128, EM);
    k_ffn2<<<g2, 256, SMEM_BYTES>>>(bd, out);
}

// round 12
// speedup vs baseline: 1.2133x; 1.0161x over previous
#include <cuda_runtime.h>
#include <cuda_fp16.h>
#include <math.h>
#include <stdint.h>

// Problem constants
#define T  8192
#define DM 1024
#define EM 8
#define HM 4096

// Tiling: BM=128, 128 smem cols (fp16), BK=32, 8 warps (2x4), warp tile 64x32
#define BM 128
#define BK 32
#define ASTRH 40     // sA row stride in halves (80B) -> conflict-free ldmatrix
#define BSTRH 136    // sB row stride in halves (272B) -> conflict-free ldmatrix
#define NSTG 3       // pipeline stages, 1 sync per k-tile

#define SA_STG (BM * ASTRH)
#define SB_STG (BK * BSTRH)
#define OFF_SB   (NSTG * SA_STG * 2)
#define OFF_TOK  (OFF_SB + NSTG * SB_STG * 2)
#define OFF_GATE (OFF_TOK + 512)
#define SMEM_BYTES (OFF_GATE + 512 + 256)

// prep_all block partition (256 threads/block, one float4 per thread)
#define ZB 8192      // zero-out + x cvt blocks: T*DM/4 = 2097152 f4 = 8192*256
#define WB 32768     // blocks per weight tensor: EM*DM*HM/4 = 8388608 f4 = 32768*256
#define RB 1024      // router blocks (T/8 warps)

// Device scratch
__device__ int    g_count[EM];
__device__ int    g_tok[EM * T];
__device__ float  g_gate[EM * T];
__device__ __half g_xh[T * DM];
__device__ __half g_wgh[EM * DM * HM];
__device__ __half g_wuh[EM * DM * HM];
__device__ __half g_wdh[EM * HM * DM];
__device__ __half g_hh[EM * T * HM];

// ---------------------------------------------------------------------------
// helpers
// ---------------------------------------------------------------------------
__device__ __forceinline__ void mma_f16(float d[4], const uint32_t a[4], const uint32_t b[2]) {
    asm volatile(
        "mma.sync.aligned.m16n8k16.row.col.f32.f16.f16.f32 "
        "{%0,%1,%2,%3}, {%4,%5,%6,%7}, {%8,%9}, {%0,%1,%2,%3};"
        : "+f"(d[0]), "+f"(d[1]), "+f"(d[2]), "+f"(d[3])
        : "r"(a[0]), "r"(a[1]), "r"(a[2]), "r"(a[3]),
          "r"(b[0]), "r"(b[1]));
}

__device__ __forceinline__ void ldsm4(uint32_t& r0, uint32_t& r1, uint32_t& r2, uint32_t& r3,
                                      uint32_t saddr) {
    asm volatile("ldmatrix.sync.aligned.m8n8.x4.shared.b16 {%0,%1,%2,%3}, [%4];"
                 : "=r"(r0), "=r"(r1), "=r"(r2), "=r"(r3) : "r"(saddr));
}
__device__ __forceinline__ void ldsm4t(uint32_t& r0, uint32_t& r1, uint32_t& r2, uint32_t& r3,
                                       uint32_t saddr) {
    asm volatile("ldmatrix.sync.aligned.m8n8.x4.trans.shared.b16 {%0,%1,%2,%3}, [%4];"
                 : "=r"(r0), "=r"(r1), "=r"(r2), "=r"(r3) : "r"(saddr));
}

__device__ __forceinline__ void cp16(void* smem_ptr, const void* gptr, bool valid) {
    uint32_t sa = (uint32_t)__cvta_generic_to_shared(smem_ptr);
    int sz = valid ? 16 : 0;
    asm volatile("cp.async.cg.shared.global [%0], [%1], 16, %2;"
                 :: "r"(sa), "l"(gptr), "r"(sz));
}
__device__ __forceinline__ void cp_commit() { asm volatile("cp.async.commit_group;"); }
template <int N>
__device__ __forceinline__ void cp_wait() { asm volatile("cp.async.wait_group %0;" :: "n"(N)); }

// ---------------------------------------------------------------------------
// prep_all: zero out + x->fp16 + Wg/Wu->fp16 + router, one launch.
// g_count must be zeroed BEFORE this kernel (memsetAsync) - router atomics.
// ---------------------------------------------------------------------------
__global__ void k_prep_all(float4* __restrict__ out, const float4* __restrict__ x4,
                           const float* __restrict__ x,
                           const float* __restrict__ Wr, const float* __restrict__ br,
                           const float4* __restrict__ Wg, const float4* __restrict__ Wu) {
    int b = blockIdx.x;
    if (b < ZB) {
        int i = b * 256 + threadIdx.x;
        out[i] = make_float4(0.f, 0.f, 0.f, 0.f);
        float4 v = x4[i];
        ((__half2*)g_xh)[2 * i    ] = __floats2half2_rn(v.x, v.y);
        ((__half2*)g_xh)[2 * i + 1] = __floats2half2_rn(v.z, v.w);
        return;
    }
    if (b < ZB + 2 * WB) {
        bool isU = (b >= ZB + WB);
        int i = (b - (isU ? ZB + WB : ZB)) * 256 + threadIdx.x;
        const float4* src = isU ? Wu : Wg;
        __half2* dst = (__half2*)(isU ? g_wuh : g_wgh);
        float4 v = src[i];
        dst[2 * i    ] = __floats2half2_rn(v.x, v.y);
        dst[2 * i + 1] = __floats2half2_rn(v.z, v.w);
        return;
    }
    // router: one warp per token
    int t    = (b - ZB - 2 * WB) * 8 + (threadIdx.x >> 5);
    int lane = threadIdx.x & 31;
    if (t >= T) return;

    const float* xr = x + (size_t)t * DM;
    float acc[EM];
#pragma unroll
    for (int e = 0; e < EM; e++) acc[e] = 0.0f;
    for (int d = lane; d < DM; d += 32) {
        float xv = xr[d];
        const float4 w0 = *(const float4*)(Wr + (size_t)d * EM);
        const float4 w1 = *(const float4*)(Wr + (size_t)d * EM + 4);
        acc[0] += xv * w0.x; acc[1] += xv * w0.y;
        acc[2] += xv * w0.z; acc[3] += xv * w0.w;
        acc[4] += xv * w1.x; acc[5] += xv * w1.y;
        acc[6] += xv * w1.z; acc[7] += xv * w1.w;
    }
#pragma unroll
    for (int e = 0; e < EM; e++) {
#pragma unroll
        for (int o = 16; o > 0; o >>= 1)
            acc[e] += __shfl_xor_sync(0xffffffffu, acc[e], o);
    }
    if (lane == 0) {
        float v[EM];
#pragma unroll
        for (int e = 0; e < EM; e++) v[e] = acc[e] + br[e];
        int b0 = 0; float m0 = v[0];
#pragma unroll
        for (int e = 1; e < EM; e++) if (v[e] > m0) { m0 = v[e]; b0 = e; }
        int b1 = -1; float m1 = -3.4e38f;
#pragma unroll
        for (int e = 0; e < EM; e++) {
            if (e == b0) continue;
            if (v[e] > m1) { m1 = v[e]; b1 = e; }
        }
        float p0 = 1.0f / (1.0f + expf(m1 - m0));
        float p1 = 1.0f - p0;
        int pos = atomicAdd(&g_count[b0], 1);
        g_tok[b0 * T + pos] = t;  g_gate[b0 * T + pos] = p0;
        pos = atomicAdd(&g_count[b1], 1);
        g_tok[b1 * T + pos] = t;  g_gate[b1 * T + pos] = p1;
    }
}

// ---------------------------------------------------------------------------
// fp16 gemm step: one BK=32 k-tile = 2 kk-steps of k16, warp tile 64x32
// (r10-proven version)
// ---------------------------------------------------------------------------
__device__ __forceinline__ void gemm_step_f16(
    uint32_t sa_base, uint32_t sb_base,
    int wm, int wn, int lane, float cc[4][4][4]) {

    const int mid = lane >> 3, mr = lane & 7;
    const int arow  = (mid & 1) * 8 + mr;
    const int akoff = (mid >> 1) * 8;
    const int bkrow = (mid & 1) * 8 + mr;
    const int bcoff = (mid >> 1) * 8;

#pragma unroll
    for (int kk = 0; kk < BK; kk += 16) {
        uint32_t af[4][4];
#pragma unroll
        for (int im = 0; im < 4; im++) {
            uint32_t addr = sa_base + ((wm + im * 16 + arow) * ASTRH + kk + akoff) * 2;
            ldsm4(af[im][0], af[im][1], af[im][2], af[im][3], addr);
        }
        uint32_t bf[4][2];
#pragma unroll
        for (int inp = 0; inp < 2; inp++) {
            uint32_t addr = sb_base + ((kk + bkrow) * BSTRH + wn + inp * 16 + bcoff) * 2;
            uint32_t r0, r1, r2, r3;
            ldsm4t(r0, r1, r2, r3, addr);
            bf[2 * inp    ][0] = r0; bf[2 * inp    ][1] = r1;
            bf[2 * inp + 1][0] = r2; bf[2 * inp + 1][1] = r3;
        }
#pragma unroll
        for (int in = 0; in < 4; in++)
#pragma unroll
            for (int im = 0; im < 4; im++)
                mma_f16(cc[im][in], af[im], bf[in]);
    }
}

// ---------------------------------------------------------------------------
// phase 1: h = silu(x@Wg+bg) * (x@Wu+bu), fp16 MMA
// z < EM: GEMM blocks. z == EM: Wd fp32->fp16 conversion (overlapped).
// grid: (T/BM, HM/64, EM+1), 256 threads, 3-stage cp.async, 1 sync/k-tile
// ---------------------------------------------------------------------------
__global__ __launch_bounds__(256) void k_ffn1(
    const float* __restrict__ bg, const float* __restrict__ bu,
    const float4* __restrict__ Wd4) {

    const int tid = threadIdx.x;

    if (blockIdx.z == EM) {
        // convert Wd concurrently with the GEMM (ffn1 never reads Wd)
        int base = (blockIdx.y * gridDim.x + blockIdx.x) * 256 + tid;   // 4096 blocks
        __half2* dst = (__half2*)g_wdh;
#pragma unroll
        for (int r = 0; r < 8; r++) {
            int i = base + r * 1048576;
            float4 v = Wd4[i];
            dst[2 * i    ] = __floats2half2_rn(v.x, v.y);
            dst[2 * i + 1] = __floats2half2_rn(v.z, v.w);
        }
        return;
    }

    const int e      = blockIdx.z;
    const int cnt    = g_count[e];
    const int m_base = blockIdx.x * BM;
    if (m_base >= cnt) return;
    const int n_base = blockIdx.y * 64;   // logical H columns

    extern __shared__ __align__(16) char smem[];
    __half* sA  = (__half*)smem;
    __half* sB  = (__half*)(smem + OFF_SB);
    int*   sTok = (int*)(smem + OFF_TOK);

    const int warp = tid >> 5, lane = tid & 31;
    const int g    = lane >> 2, tq  = lane & 3;
    const int wm   = (warp & 1) * 64;
    const int wn   = (warp >> 1) * 32;

    if (tid < BM) {
        int r = m_base + tid;
        sTok[tid] = (r < cnt) ? g_tok[e * T + r] : 0;
    }
    __syncthreads();

    float cc[4][4][4];
#pragma unroll
    for (int a = 0; a < 4; a++)
#pragma unroll
        for (int b = 0; b < 4; b++)
#pragma unroll
            for (int c = 0; c < 4; c++) cc[a][b][c] = 0.0f;

    const __half* wg = g_wgh + (size_t)e * DM * HM + n_base;
    const __half* wu = g_wuh + (size_t)e * DM * HM + n_base;

    auto load_tiles = [&](int st, int k0) {
#pragma unroll
        for (int j = 0; j < 2; j++) {          // A: 128 rows x 32 halves
            int idx = tid + j * 256;
            int row = idx >> 2;
            int c8  = (idx & 3) << 3;
            cp16(&sA[st * SA_STG + row * ASTRH + c8],
                 g_xh + (size_t)sTok[row] * DM + k0 + c8, true);
        }
#pragma unroll
        for (int j = 0; j < 2; j++) {          // B: 32 rows x 128 halves (16 n8-chunks)
            int idx = tid + j * 256;
            int kr  = idx >> 4;
            int q   = idx & 15;                // even=Wg, odd=Wu
            const __half* src = (q & 1) ? wu : wg;
            cp16(&sB[st * SB_STG + kr * BSTRH + (q << 3)],
                 src + (size_t)(k0 + kr) * HM + ((q >> 1) << 3), true);
        }
        cp_commit();
    };

    uint32_t sa0 = (uint32_t)__cvta_generic_to_shared(sA);
    uint32_t sb0 = (uint32_t)__cvta_generic_to_shared(sB);
    const uint32_t saSz = SA_STG * 2, sbSz = SB_STG * 2;

    load_tiles(0, 0);
    load_tiles(1, BK);
    const int KT = DM / BK;   // 32
    int cur = 0, nxt = 2;
    for (int kt = 0; kt < KT; kt++) {
        if (kt + 2 < KT) cp_wait<1>(); else cp_wait<0>();
        __syncthreads();
        if (kt + 2 < KT) load_tiles(nxt, (kt + 2) * BK);
        gemm_step_f16(sa0 + cur * saSz, sb0 + cur * sbSz, wm, wn, lane, cc);
        cur = (cur == NSTG - 1) ? 0 : cur + 1;
        nxt = (nxt == NSTG - 1) ? 0 : nxt + 1;
    }

    // epilogue: in=2j -> gate, in=2j+1 -> up, same logical cols, register silu
    const float* bge = bg + (size_t)e * HM;
    const float* bue = bu + (size_t)e * HM;
    __half* hb = g_hh + (size_t)e * T * HM;
#pragma unroll
    for (int im = 0; im < 4; im++) {
        int r0 = m_base + wm + im * 16 + g;
#pragma unroll
        for (int j = 0; j < 2; j++) {
            int c0 = n_base + ((wn >> 4) + j) * 8 + 2 * tq;
            float bg0 = bge[c0], bg1 = bge[c0 + 1];
            float bu0 = bue[c0], bu1 = bue[c0 + 1];
            if (r0 < cnt) {
                float gv0 = cc[im][2 * j][0] + bg0, gv1 = cc[im][2 * j][1] + bg1;
                float uv0 = cc[im][2 * j + 1][0] + bu0, uv1 = cc[im][2 * j + 1][1] + bu1;
                *(__half2*)(hb + (size_t)r0 * HM + c0) = __floats2half2_rn(
                    gv0 / (1.0f + expf(-gv0)) * uv0,
                    gv1 / (1.0f + expf(-gv1)) * uv1);
            }
            if (r0 + 8 < cnt) {
                float gv0 = cc[im][2 * j][2] + bg0, gv1 = cc[im][2 * j][3] + bg1;
                float uv0 = cc[im][2 * j + 1][2] + bu0, uv1 = cc[im][2 * j + 1][3] + bu1;
                *(__half2*)(hb + (size_t)(r0 + 8) * HM + c0) = __floats2half2_rn(
                    gv0 / (1.0f + expf(-gv0)) * uv0,
                    gv1 / (1.0f + expf(-gv1)) * uv1);
            }
        }
    }
}

// ---------------------------------------------------------------------------
// phase 2: out[tok] += gate * (h @ Wd + bd), fp16 MMA
// grid: (T/BM, DM/128, EM), 256 threads, 3-stage cp.async, 1 sync/k-tile
// ---------------------------------------------------------------------------
__global__ __launch_bounds__(256) void k_ffn2(
    const float* __restrict__ bd, float* __restrict__ out) {

    const int e      = blockIdx.z;
    const int cnt    = g_count[e];
    const int m_base = blockIdx.x * BM;
    if (m_base >= cnt) return;
    const int n_base = blockIdx.y * 128;

    extern __shared__ __align__(16) char smem[];
    __half* sA   = (__half*)smem;
    __half* sB   = (__half*)(smem + OFF_SB);
    int*   sTok  = (int*)(smem + OFF_TOK);
    float* sGate = (float*)(smem + OFF_GATE);

    const int tid  = threadIdx.x;
    const int warp = tid >> 5, lane = tid & 31;
    const int g    = lane >> 2, tq  = lane & 3;
    const int wm   = (warp & 1) * 64;
    const int wn   = (warp >> 1) * 32;

    if (tid < BM) {
        int r = m_base + tid;
        sTok[tid]  = (r < cnt) ? g_tok[e * T + r]  : 0;
        sGate[tid] = (r < cnt) ? g_gate[e * T + r] : 0.0f;
    }

    float cc[4][4][4];
#pragma unroll
    for (int a = 0; a < 4; a++)
#pragma unroll
        for (int b = 0; b < 4; b++)
#pragma unroll
            for (int c = 0; c < 4; c++) cc[a][b][c] = 0.0f;

    const __half* hb = g_hh + (size_t)e * T * HM;
    const __half* wd = g_wdh + (size_t)e * HM * DM + n_base;

    auto load_tiles = [&](int st, int k0) {
#pragma unroll
        for (int j = 0; j < 2; j++) {          // A: 128 slot rows x 32 halves (zfill)
            int idx = tid + j * 256;
            int row = idx >> 2;
            int c8  = (idx & 3) << 3;
            bool v  = (m_base + row) < cnt;
            cp16(&sA[st * SA_STG + row * ASTRH + c8],
                 hb + (size_t)(m_base + row) * HM + k0 + c8, v);
        }
#pragma unroll
        for (int j = 0; j < 2; j++) {          // B: 32 rows x 128 halves
            int idx = tid + j * 256;
            int kr  = idx >> 4;
            int c8  = (idx & 15) << 3;
            cp16(&sB[st * SB_STG + kr * BSTRH + c8],
                 wd + (size_t)(k0 + kr) * DM + c8, true);
        }
        cp_commit();
    };

    uint32_t sa0 = (uint32_t)__cvta_generic_to_shared(sA);
    uint32_t sb0 = (uint32_t)__cvta_generic_to_shared(sB);
    const uint32_t saSz = SA_STG * 2, sbSz = SB_STG * 2;

    load_tiles(0, 0);
    load_tiles(1, BK);
    const int KT = HM / BK;   // 128
    int cur = 0, nxt = 2;
    for (int kt = 0; kt < KT; kt++) {
        if (kt + 2 < KT) cp_wait<1>(); else cp_wait<0>();
        __syncthreads();
        if (kt + 2 < KT) load_tiles(nxt, (kt + 2) * BK);
        gemm_step_f16(sa0 + cur * saSz, sb0 + cur * sbSz, wm, wn, lane, cc);
        cur = (cur == NSTG - 1) ? 0 : cur + 1;
        nxt = (nxt == NSTG - 1) ? 0 : nxt + 1;
    }

    // epilogue: gate-weighted scatter atomicAdd
    const float* bde = bd + (size_t)e * DM;
#pragma unroll
    for (int im = 0; im < 4; im++) {
        int rl = wm + im * 16 + g;
        int rg = m_base + rl;
#pragma unroll
        for (int in = 0; in < 4; in++) {
            int n = n_base + wn + in * 8 + tq * 2;
            float b0 = bde[n], b1 = bde[n + 1];
            if (rg < cnt) {
                int   t  = sTok[rl];
                float gt = sGate[rl];
                atomicAdd(&out[(size_t)t * DM + n    ], gt * (cc[im][in][0] + b0));
                atomicAdd(&out[(size_t)t * DM + n + 1], gt * (cc[im][in][1] + b1));
            }
            if (rg + 8 < cnt) {
                int   t  = sTok[rl + 8];
                float gt = sGate[rl + 8];
                atomicAdd(&out[(size_t)t * DM + n    ], gt * (cc[im][in][2] + b0));
                atomicAdd(&out[(size_t)t * DM + n + 1], gt * (cc[im][in][3] + b1));
            }
        }
    }
}

// ---------------------------------------------------------------------------
extern "C" void kernel_launch(void* const* d_in, const int* in_sizes, int n_in,
                              void* d_out, int out_size) {
    const float* x  = (const float*)d_in[0];
    const float* Wr = (const float*)d_in[1];
    const float* br = (const float*)d_in[2];
    const float* Wg = (const float*)d_in[3];
    const float* bg = (const float*)d_in[4];
    const float* Wu = (const float*)d_in[5];
    const float* bu = (const float*)d_in[6];
    const float* Wd = (const float*)d_in[7];
    const float* bd = (const float*)d_in[8];
    float* out = (float*)d_out;

    cudaFuncSetAttribute(k_ffn1, cudaFuncAttributeMaxDynamicSharedMemorySize, SMEM_BYTES);
    cudaFuncSetAttribute(k_ffn2, cudaFuncAttributeMaxDynamicSharedMemorySize, SMEM_BYTES);

    // zero router counters (router atomics live in k_prep_all)
    void* cnt_ptr;
    cudaGetSymbolAddress(&cnt_ptr, g_count);
    cudaMemsetAsync(cnt_ptr, 0, EM * sizeof(int));

    // fused prep: zero out + x cvt + Wg/Wu cvt + router
    k_prep_all<<<ZB + 2 * WB + RB, 256>>>(
        (float4*)out, (const float4*)x, x, Wr, br,
        (const float4*)Wg, (const float4*)Wu);

    // ffn1 GEMM + overlapped Wd conversion (z == EM plane)
    dim3 g1(T / BM, HM / 64, EM + 1);
    k_ffn1<<<g1, 256, SMEM_BYTES>>>(bg, bu, (const float4*)Wd);

    dim3 g2(T / BM, DM / 128, EM);
    k_ffn2<<<g2, 256, SMEM_BYTES>>>(bd, out);
}

// round 13
// speedup vs baseline: 1.2729x; 1.0491x over previous
#include <cuda_runtime.h>
#include <cuda_fp16.h>
#include <math.h>
#include <stdint.h>

// Problem constants
#define T  8192
#define DM 1024
#define EM 8
#define HM 4096

// Tiling: BM=128, 128 smem cols (fp16), BK=32, 8 warps (2x4), warp tile 64x32
#define BM 128
#define BK 32
#define ASTRH 40     // sA row stride in halves (80B) -> conflict-free ldmatrix
#define BSTRH 136    // sB row stride in halves (272B) -> conflict-free ldmatrix
#define NSTG 3       // pipeline stages, 1 sync per k-tile

#define SA_STG (BM * ASTRH)
#define SB_STG (BK * BSTRH)
#define OFF_SB   (NSTG * SA_STG * 2)
#define OFF_TOK  (OFF_SB + NSTG * SB_STG * 2)
#define OFF_GATE (OFF_TOK + 512)
#define SMEM_BYTES (OFF_GATE + 512 + 256)

// prep_all block partition (256 threads/block, one float4 per thread)
#define ZB 8192      // zero-out + x cvt blocks: T*DM/4 = 2097152 f4 = 8192*256
#define WB 32768     // blocks per weight tensor: EM*DM*HM/4 = 8388608 f4 = 32768*256
#define RB 1024      // router blocks (T/8 warps)

// Device scratch
__device__ int    g_count[EM];
__device__ int    g_tok[EM * T];
__device__ float  g_gate[EM * T];
__device__ __half g_xh[T * DM];
__device__ __half g_wgh[EM * DM * HM];
__device__ __half g_wuh[EM * DM * HM];
__device__ __half g_wdh[EM * HM * DM];
__device__ __half g_hh[EM * T * HM];

// ---------------------------------------------------------------------------
// helpers
// ---------------------------------------------------------------------------
__device__ __forceinline__ void mma_f16(float d[4], const uint32_t a[4], const uint32_t b[2]) {
    asm volatile(
        "mma.sync.aligned.m16n8k16.row.col.f32.f16.f16.f32 "
        "{%0,%1,%2,%3}, {%4,%5,%6,%7}, {%8,%9}, {%0,%1,%2,%3};"
        : "+f"(d[0]), "+f"(d[1]), "+f"(d[2]), "+f"(d[3])
        : "r"(a[0]), "r"(a[1]), "r"(a[2]), "r"(a[3]),
          "r"(b[0]), "r"(b[1]));
}

__device__ __forceinline__ void ldsm4(uint32_t& r0, uint32_t& r1, uint32_t& r2, uint32_t& r3,
                                      uint32_t saddr) {
    asm volatile("ldmatrix.sync.aligned.m8n8.x4.shared.b16 {%0,%1,%2,%3}, [%4];"
                 : "=r"(r0), "=r"(r1), "=r"(r2), "=r"(r3) : "r"(saddr));
}
__device__ __forceinline__ void ldsm4t(uint32_t& r0, uint32_t& r1, uint32_t& r2, uint32_t& r3,
                                       uint32_t saddr) {
    asm volatile("ldmatrix.sync.aligned.m8n8.x4.trans.shared.b16 {%0,%1,%2,%3}, [%4];"
                 : "=r"(r0), "=r"(r1), "=r"(r2), "=r"(r3) : "r"(saddr));
}

__device__ __forceinline__ void cp16(void* smem_ptr, const void* gptr, bool valid) {
    uint32_t sa = (uint32_t)__cvta_generic_to_shared(smem_ptr);
    int sz = valid ? 16 : 0;
    asm volatile("cp.async.cg.shared.global [%0], [%1], 16, %2;"
                 :: "r"(sa), "l"(gptr), "r"(sz));
}
__device__ __forceinline__ void cp_commit() { asm volatile("cp.async.commit_group;"); }
template <int N>
__device__ __forceinline__ void cp_wait() { asm volatile("cp.async.wait_group %0;" :: "n"(N)); }

// ---------------------------------------------------------------------------
// prep_all: zero out + x->fp16 + Wg/Wu->fp16 + router, one launch.
// g_count must be zeroed BEFORE this kernel (memsetAsync) - router atomics.
// ---------------------------------------------------------------------------
__global__ void k_prep_all(float4* __restrict__ out, const float4* __restrict__ x4,
                           const float* __restrict__ x,
                           const float* __restrict__ Wr, const float* __restrict__ br,
                           const float4* __restrict__ Wg, const float4* __restrict__ Wu) {
    int b = blockIdx.x;
    if (b < ZB) {
        int i = b * 256 + threadIdx.x;
        out[i] = make_float4(0.f, 0.f, 0.f, 0.f);
        float4 v = x4[i];
        ((__half2*)g_xh)[2 * i    ] = __floats2half2_rn(v.x, v.y);
        ((__half2*)g_xh)[2 * i + 1] = __floats2half2_rn(v.z, v.w);
        return;
    }
    if (b < ZB + 2 * WB) {
        bool isU = (b >= ZB + WB);
        int i = (b - (isU ? ZB + WB : ZB)) * 256 + threadIdx.x;
        const float4* src = isU ? Wu : Wg;
        __half2* dst = (__half2*)(isU ? g_wuh : g_wgh);
        float4 v = src[i];
        dst[2 * i    ] = __floats2half2_rn(v.x, v.y);
        dst[2 * i + 1] = __floats2half2_rn(v.z, v.w);
        return;
    }
    // router: one warp per token
    int t    = (b - ZB - 2 * WB) * 8 + (threadIdx.x >> 5);
    int lane = threadIdx.x & 31;
    if (t >= T) return;

    const float* xr = x + (size_t)t * DM;
    float acc[EM];
#pragma unroll
    for (int e = 0; e < EM; e++) acc[e] = 0.0f;
    for (int d = lane; d < DM; d += 32) {
        float xv = xr[d];
        const float4 w0 = *(const float4*)(Wr + (size_t)d * EM);
        const float4 w1 = *(const float4*)(Wr + (size_t)d * EM + 4);
        acc[0] += xv * w0.x; acc[1] += xv * w0.y;
        acc[2] += xv * w0.z; acc[3] += xv * w0.w;
        acc[4] += xv * w1.x; acc[5] += xv * w1.y;
        acc[6] += xv * w1.z; acc[7] += xv * w1.w;
    }
#pragma unroll
    for (int e = 0; e < EM; e++) {
#pragma unroll
        for (int o = 16; o > 0; o >>= 1)
            acc[e] += __shfl_xor_sync(0xffffffffu, acc[e], o);
    }
    if (lane == 0) {
        float v[EM];
#pragma unroll
        for (int e = 0; e < EM; e++) v[e] = acc[e] + br[e];
        int b0 = 0; float m0 = v[0];
#pragma unroll
        for (int e = 1; e < EM; e++) if (v[e] > m0) { m0 = v[e]; b0 = e; }
        int b1 = -1; float m1 = -3.4e38f;
#pragma unroll
        for (int e = 0; e < EM; e++) {
            if (e == b0) continue;
            if (v[e] > m1) { m1 = v[e]; b1 = e; }
        }
        float p0 = 1.0f / (1.0f + expf(m1 - m0));
        float p1 = 1.0f - p0;
        int pos = atomicAdd(&g_count[b0], 1);
        g_tok[b0 * T + pos] = t;  g_gate[b0 * T + pos] = p0;
        pos = atomicAdd(&g_count[b1], 1);
        g_tok[b1 * T + pos] = t;  g_gate[b1 * T + pos] = p1;
    }
}

// ---------------------------------------------------------------------------
// fp16 gemm step: one BK=32 k-tile, warp tile 64x32.
// HOISTED: all 12 LDSM (both kk-steps) issued before all 32 MMAs,
// so the 2nd step's loads overlap the 1st step's MMA drain.
// ---------------------------------------------------------------------------
__device__ __forceinline__ void gemm_step_f16(
    uint32_t sa_base, uint32_t sb_base,
    int wm, int wn, int lane, float cc[4][4][4]) {

    const int mid = lane >> 3, mr = lane & 7;
    const int arow  = (mid & 1) * 8 + mr;
    const int akoff = (mid >> 1) * 8;
    const int bkrow = (mid & 1) * 8 + mr;
    const int bcoff = (mid >> 1) * 8;

    uint32_t af[2][4][4];
    uint32_t bf[2][4][2];
#pragma unroll
    for (int s = 0; s < 2; s++) {
        const int kk = s * 16;
#pragma unroll
        for (int im = 0; im < 4; im++) {
            uint32_t addr = sa_base + ((wm + im * 16 + arow) * ASTRH + kk + akoff) * 2;
            ldsm4(af[s][im][0], af[s][im][1], af[s][im][2], af[s][im][3], addr);
        }
#pragma unroll
        for (int inp = 0; inp < 2; inp++) {
            uint32_t addr = sb_base + ((kk + bkrow) * BSTRH + wn + inp * 16 + bcoff) * 2;
            uint32_t r0, r1, r2, r3;
            ldsm4t(r0, r1, r2, r3, addr);
            bf[s][2 * inp    ][0] = r0; bf[s][2 * inp    ][1] = r1;
            bf[s][2 * inp + 1][0] = r2; bf[s][2 * inp + 1][1] = r3;
        }
    }
#pragma unroll
    for (int s = 0; s < 2; s++)
#pragma unroll
        for (int in = 0; in < 4; in++)
#pragma unroll
            for (int im = 0; im < 4; im++)
                mma_f16(cc[im][in], af[s][im], bf[s][in]);
}

// ---------------------------------------------------------------------------
// phase 1: h = silu(x@Wg+bg) * (x@Wu+bu), fp16 MMA
// z < EM: GEMM blocks. z == EM: Wd fp32->fp16 conversion (overlapped).
// grid: (T/BM, HM/64, EM+1), 256 threads, 3-stage cp.async, 1 sync/k-tile
// ---------------------------------------------------------------------------
__global__ __launch_bounds__(256, 2) void k_ffn1(
    const float* __restrict__ bg, const float* __restrict__ bu,
    const float4* __restrict__ Wd4) {

    const int tid = threadIdx.x;

    if (blockIdx.z == EM) {
        // convert Wd concurrently with the GEMM (ffn1 never reads Wd)
        int base = (blockIdx.y * gridDim.x + blockIdx.x) * 256 + tid;   // 4096 blocks
        __half2* dst = (__half2*)g_wdh;
#pragma unroll
        for (int r = 0; r < 8; r++) {
            int i = base + r * 1048576;
            float4 v = Wd4[i];
            dst[2 * i    ] = __floats2half2_rn(v.x, v.y);
            dst[2 * i + 1] = __floats2half2_rn(v.z, v.w);
        }
        return;
    }

    const int e      = blockIdx.z;
    const int cnt    = g_count[e];
    const int m_base = blockIdx.x * BM;
    if (m_base >= cnt) return;
    const int n_base = blockIdx.y * 64;   // logical H columns

    extern __shared__ __align__(16) char smem[];
    __half* sA  = (__half*)smem;
    __half* sB  = (__half*)(smem + OFF_SB);
    int*   sTok = (int*)(smem + OFF_TOK);

    const int warp = tid >> 5, lane = tid & 31;
    const int g    = lane >> 2, tq  = lane & 3;
    const int wm   = (warp & 1) * 64;
    const int wn   = (warp >> 1) * 32;

    if (tid < BM) {
        int r = m_base + tid;
        sTok[tid] = (r < cnt) ? g_tok[e * T + r] : 0;
    }
    __syncthreads();

    float cc[4][4][4];
#pragma unroll
    for (int a = 0; a < 4; a++)
#pragma unroll
        for (int b = 0; b < 4; b++)
#pragma unroll
            for (int c = 0; c < 4; c++) cc[a][b][c] = 0.0f;

    const __half* wg = g_wgh + (size_t)e * DM * HM + n_base;
    const __half* wu = g_wuh + (size_t)e * DM * HM + n_base;

    auto load_tiles = [&](int st, int k0) {
#pragma unroll
        for (int j = 0; j < 2; j++) {          // A: 128 rows x 32 halves
            int idx = tid + j * 256;
            int row = idx >> 2;
            int c8  = (idx & 3) << 3;
            cp16(&sA[st * SA_STG + row * ASTRH + c8],
                 g_xh + (size_t)sTok[row] * DM + k0 + c8, true);
        }
#pragma unroll
        for (int j = 0; j < 2; j++) {          // B: 32 rows x 128 halves (16 n8-chunks)
            int idx = tid + j * 256;
            int kr  = idx >> 4;
            int q   = idx & 15;                // even=Wg, odd=Wu
            const __half* src = (q & 1) ? wu : wg;
            cp16(&sB[st * SB_STG + kr * BSTRH + (q << 3)],
                 src + (size_t)(k0 + kr) * HM + ((q >> 1) << 3), true);
        }
        cp_commit();
    };

    uint32_t sa0 = (uint32_t)__cvta_generic_to_shared(sA);
    uint32_t sb0 = (uint32_t)__cvta_generic_to_shared(sB);
    const uint32_t saSz = SA_STG * 2, sbSz = SB_STG * 2;

    load_tiles(0, 0);
    load_tiles(1, BK);
    const int KT = DM / BK;   // 32
    int cur = 0, nxt = 2;
    for (int kt = 0; kt < KT; kt++) {
        if (kt + 2 < KT) cp_wait<1>(); else cp_wait<0>();
        __syncthreads();
        if (kt + 2 < KT) load_tiles(nxt, (kt + 2) * BK);
        gemm_step_f16(sa0 + cur * saSz, sb0 + cur * sbSz, wm, wn, lane, cc);
        cur = (cur == NSTG - 1) ? 0 : cur + 1;
        nxt = (nxt == NSTG - 1) ? 0 : nxt + 1;
    }

    // epilogue: in=2j -> gate, in=2j+1 -> up, same logical cols, register silu
    const float* bge = bg + (size_t)e * HM;
    const float* bue = bu + (size_t)e * HM;
    __half* hb = g_hh + (size_t)e * T * HM;
#pragma unroll
    for (int im = 0; im < 4; im++) {
        int r0 = m_base + wm + im * 16 + g;
#pragma unroll
        for (int j = 0; j < 2; j++) {
            int c0 = n_base + ((wn >> 4) + j) * 8 + 2 * tq;
            float bg0 = bge[c0], bg1 = bge[c0 + 1];
            float bu0 = bue[c0], bu1 = bue[c0 + 1];
            if (r0 < cnt) {
                float gv0 = cc[im][2 * j][0] + bg0, gv1 = cc[im][2 * j][1] + bg1;
                float uv0 = cc[im][2 * j + 1][0] + bu0, uv1 = cc[im][2 * j + 1][1] + bu1;
                *(__half2*)(hb + (size_t)r0 * HM + c0) = __floats2half2_rn(
                    gv0 / (1.0f + expf(-gv0)) * uv0,
                    gv1 / (1.0f + expf(-gv1)) * uv1);
            }
            if (r0 + 8 < cnt) {
                float gv0 = cc[im][2 * j][2] + bg0, gv1 = cc[im][2 * j][3] + bg1;
                float uv0 = cc[im][2 * j + 1][2] + bu0, uv1 = cc[im][2 * j + 1][3] + bu1;
                *(__half2*)(hb + (size_t)(r0 + 8) * HM + c0) = __floats2half2_rn(
                    gv0 / (1.0f + expf(-gv0)) * uv0,
                    gv1 / (1.0f + expf(-gv1)) * uv1);
            }
        }
    }
}

// ---------------------------------------------------------------------------
// phase 2: out[tok] += gate * (h @ Wd + bd), fp16 MMA
// grid: (T/BM, DM/128, EM), 256 threads, 3-stage cp.async, 1 sync/k-tile
// ---------------------------------------------------------------------------
__global__ __launch_bounds__(256, 2) void k_ffn2(
    const float* __restrict__ bd, float* __restrict__ out) {

    const int e      = blockIdx.z;
    const int cnt    = g_count[e];
    const int m_base = blockIdx.x * BM;
    if (m_base >= cnt) return;
    const int n_base = blockIdx.y * 128;

    extern __shared__ __align__(16) char smem[];
    __half* sA   = (__half*)smem;
    __half* sB   = (__half*)(smem + OFF_SB);
    int*   sTok  = (int*)(smem + OFF_TOK);
    float* sGate = (float*)(smem + OFF_GATE);

    const int tid  = threadIdx.x;
    const int warp = tid >> 5, lane = tid & 31;
    const int g    = lane >> 2, tq  = lane & 3;
    const int wm   = (warp & 1) * 64;
    const int wn   = (warp >> 1) * 32;

    if (tid < BM) {
        int r = m_base + tid;
        sTok[tid]  = (r < cnt) ? g_tok[e * T + r]  : 0;
        sGate[tid] = (r < cnt) ? g_gate[e * T + r] : 0.0f;
    }

    float cc[4][4][4];
#pragma unroll
    for (int a = 0; a < 4; a++)
#pragma unroll
        for (int b = 0; b < 4; b++)
#pragma unroll
            for (int c = 0; c < 4; c++) cc[a][b][c] = 0.0f;

    const __half* hb = g_hh + (size_t)e * T * HM;
    const __half* wd = g_wdh + (size_t)e * HM * DM + n_base;

    auto load_tiles = [&](int st, int k0) {
#pragma unroll
        for (int j = 0; j < 2; j++) {          // A: 128 slot rows x 32 halves (zfill)
            int idx = tid + j * 256;
            int row = idx >> 2;
            int c8  = (idx & 3) << 3;
            bool v  = (m_base + row) < cnt;
            cp16(&sA[st * SA_STG + row * ASTRH + c8],
                 hb + (size_t)(m_base + row) * HM + k0 + c8, v);
        }
#pragma unroll
        for (int j = 0; j < 2; j++) {          // B: 32 rows x 128 halves
            int idx = tid + j * 256;
            int kr  = idx >> 4;
            int c8  = (idx & 15) << 3;
            cp16(&sB[st * SB_STG + kr * BSTRH + c8],
                 wd + (size_t)(k0 + kr) * DM + c8, true);
        }
        cp_commit();
    };

    uint32_t sa0 = (uint32_t)__cvta_generic_to_shared(sA);
    uint32_t sb0 = (uint32_t)__cvta_generic_to_shared(sB);
    const uint32_t saSz = SA_STG * 2, sbSz = SB_STG * 2;

    load_tiles(0, 0);
    load_tiles(1, BK);
    const int KT = HM / BK;   // 128
    int cur = 0, nxt = 2;
    for (int kt = 0; kt < KT; kt++) {
        if (kt + 2 < KT) cp_wait<1>(); else cp_wait<0>();
        __syncthreads();
        if (kt + 2 < KT) load_tiles(nxt, (kt + 2) * BK);
        gemm_step_f16(sa0 + cur * saSz, sb0 + cur * sbSz, wm, wn, lane, cc);
        cur = (cur == NSTG - 1) ? 0 : cur + 1;
        nxt = (nxt == NSTG - 1) ? 0 : nxt + 1;
    }

    // epilogue: gate-weighted scatter atomicAdd
    const float* bde = bd + (size_t)e * DM;
#pragma unroll
    for (int im = 0; im < 4; im++) {
        int rl = wm + im * 16 + g;
        int rg = m_base + rl;
#pragma unroll
        for (int in = 0; in < 4; in++) {
            int n = n_base + wn + in * 8 + tq * 2;
            float b0 = bde[n], b1 = bde[n + 1];
            if (rg < cnt) {
                int   t  = sTok[rl];
                float gt = sGate[rl];
                atomicAdd(&out[(size_t)t * DM + n    ], gt * (cc[im][in][0] + b0));
                atomicAdd(&out[(size_t)t * DM + n + 1], gt * (cc[im][in][1] + b1));
            }
            if (rg + 8 < cnt) {
                int   t  = sTok[rl + 8];
                float gt = sGate[rl + 8];
                atomicAdd(&out[(size_t)t * DM + n    ], gt * (cc[im][in][2] + b0));
                atomicAdd(&out[(size_t)t * DM + n + 1], gt * (cc[im][in][3] + b1));
            }
        }
    }
}

// ---------------------------------------------------------------------------
extern "C" void kernel_launch(void* const* d_in, const int* in_sizes, int n_in,
                              void* d_out, int out_size) {
    const float* x  = (const float*)d_in[0];
    const float* Wr = (const float*)d_in[1];
    const float* br = (const float*)d_in[2];
    const float* Wg = (const float*)d_in[3];
    const float* bg = (const float*)d_in[4];
    const float* Wu = (const float*)d_in[5];
    const float* bu = (const float*)d_in[6];
    const float* Wd = (const float*)d_in[7];
    const float* bd = (const float*)d_in[8];
    float* out = (float*)d_out;

    cudaFuncSetAttribute(k_ffn1, cudaFuncAttributeMaxDynamicSharedMemorySize, SMEM_BYTES);
    cudaFuncSetAttribute(k_ffn2, cudaFuncAttributeMaxDynamicSharedMemorySize, SMEM_BYTES);

    // zero router counters (router atomics live in k_prep_all)
    void* cnt_ptr;
    cudaGetSymbolAddress(&cnt_ptr, g_count);
    cudaMemsetAsync(cnt_ptr, 0, EM * sizeof(int));

    // fused prep: zero out + x cvt + Wg/Wu cvt + router
    k_prep_all<<<ZB + 2 * WB + RB, 256>>>(
        (float4*)out, (const float4*)x, x, Wr, br,
        (const float4*)Wg, (const float4*)Wu);

    // ffn1 GEMM + overlapped Wd conversion (z == EM plane)
    dim3 g1(T / BM, HM / 64, EM + 1);
    k_ffn1<<<g1, 256, SMEM_BYTES>>>(bg, bu, (const float4*)Wd);

    dim3 g2(T / BM, DM / 128, EM);
    k_ffn2<<<g2, 256, SMEM_BYTES>>>(bd, out);
}

// round 14
// speedup vs baseline: 1.2826x; 1.0076x over previous
#include <cuda_runtime.h>
#include <cuda_fp16.h>
#include <math.h>
#include <stdint.h>

// Problem constants
#define T  8192
#define DM 1024
#define EM 8
#define HM 4096

// Tiling: BM=128, 128 smem cols (fp16), BK=32, 8 warps (2x4), warp tile 64x32
#define BM 128
#define BK 32
#define ASTRH 40     // sA row stride in halves (80B) -> conflict-free ldmatrix
#define BSTRH 136    // sB row stride in halves (272B) -> conflict-free ldmatrix
#define NSTG 4       // pipeline stages (power of 2), 1 sync per k-tile

#define SA_STG (BM * ASTRH)
#define SB_STG (BK * BSTRH)
#define OFF_SB   (NSTG * SA_STG * 2)
#define OFF_TOK  (OFF_SB + NSTG * SB_STG * 2)
#define OFF_GATE (OFF_TOK + 512)
#define SMEM_BYTES (OFF_GATE + 512 + 256)

// prep_all block partition (256 threads/block, FOUR float4 per thread -> 1024 f4/block)
#define ZB 2048      // zero-out + x cvt: T*DM/4 = 2097152 f4 = 2048*1024
#define WB 8192      // per weight tensor: EM*DM*HM/4 = 8388608 f4 = 8192*1024
#define RB 1024      // router blocks (T/8 warps)

// Device scratch
__device__ int    g_count[EM];
__device__ int    g_tok[EM * T];
__device__ float  g_gate[EM * T];
__device__ __half g_xh[T * DM];
__device__ __half g_wgh[EM * DM * HM];
__device__ __half g_wuh[EM * DM * HM];
__device__ __half g_wdh[EM * HM * DM];
__device__ __half g_hh[EM * T * HM];

// ---------------------------------------------------------------------------
// helpers
// ---------------------------------------------------------------------------
__device__ __forceinline__ void mma_f16(float d[4], const uint32_t a[4], const uint32_t b[2]) {
    asm volatile(
        "mma.sync.aligned.m16n8k16.row.col.f32.f16.f16.f32 "
        "{%0,%1,%2,%3}, {%4,%5,%6,%7}, {%8,%9}, {%0,%1,%2,%3};"
        : "+f"(d[0]), "+f"(d[1]), "+f"(d[2]), "+f"(d[3])
        : "r"(a[0]), "r"(a[1]), "r"(a[2]), "r"(a[3]),
          "r"(b[0]), "r"(b[1]));
}

__device__ __forceinline__ void ldsm4(uint32_t& r0, uint32_t& r1, uint32_t& r2, uint32_t& r3,
                                      uint32_t saddr) {
    asm volatile("ldmatrix.sync.aligned.m8n8.x4.shared.b16 {%0,%1,%2,%3}, [%4];"
                 : "=r"(r0), "=r"(r1), "=r"(r2), "=r"(r3) : "r"(saddr));
}
__device__ __forceinline__ void ldsm4t(uint32_t& r0, uint32_t& r1, uint32_t& r2, uint32_t& r3,
                                       uint32_t saddr) {
    asm volatile("ldmatrix.sync.aligned.m8n8.x4.trans.shared.b16 {%0,%1,%2,%3}, [%4];"
                 : "=r"(r0), "=r"(r1), "=r"(r2), "=r"(r3) : "r"(saddr));
}

__device__ __forceinline__ void cp16(void* smem_ptr, const void* gptr, bool valid) {
    uint32_t sa = (uint32_t)__cvta_generic_to_shared(smem_ptr);
    int sz = valid ? 16 : 0;
    asm volatile("cp.async.cg.shared.global [%0], [%1], 16, %2;"
                 :: "r"(sa), "l"(gptr), "r"(sz));
}
__device__ __forceinline__ void cp_commit() { asm volatile("cp.async.commit_group;"); }
template <int N>
__device__ __forceinline__ void cp_wait() { asm volatile("cp.async.wait_group %0;" :: "n"(N)); }

// ---------------------------------------------------------------------------
// prep_all: zero out + x->fp16 + Wg/Wu->fp16 + router, one launch.
// 4 float4 per thread (MLP=4 overlaps DRAM latency).
// g_count must be zeroed BEFORE this kernel (memsetAsync) - router atomics.
// ---------------------------------------------------------------------------
__global__ void k_prep_all(float4* __restrict__ out, const float4* __restrict__ x4,
                           const float* __restrict__ x,
                           const float* __restrict__ Wr, const float* __restrict__ br,
                           const float4* __restrict__ Wg, const float4* __restrict__ Wu) {
    int b = blockIdx.x;
    if (b < ZB) {
        int i0 = b * 1024 + threadIdx.x;
        float4 v[4];
#pragma unroll
        for (int j = 0; j < 4; j++) v[j] = x4[i0 + j * 256];
#pragma unroll
        for (int j = 0; j < 4; j++) {
            int i = i0 + j * 256;
            out[i] = make_float4(0.f, 0.f, 0.f, 0.f);
            ((__half2*)g_xh)[2 * i    ] = __floats2half2_rn(v[j].x, v[j].y);
            ((__half2*)g_xh)[2 * i + 1] = __floats2half2_rn(v[j].z, v[j].w);
        }
        return;
    }
    if (b < ZB + 2 * WB) {
        bool isU = (b >= ZB + WB);
        int i0 = (b - (isU ? ZB + WB : ZB)) * 1024 + threadIdx.x;
        const float4* src = isU ? Wu : Wg;
        __half2* dst = (__half2*)(isU ? g_wuh : g_wgh);
        float4 v[4];
#pragma unroll
        for (int j = 0; j < 4; j++) v[j] = src[i0 + j * 256];
#pragma unroll
        for (int j = 0; j < 4; j++) {
            int i = i0 + j * 256;
            dst[2 * i    ] = __floats2half2_rn(v[j].x, v[j].y);
            dst[2 * i + 1] = __floats2half2_rn(v[j].z, v[j].w);
        }
        return;
    }
    // router: one warp per token
    int t    = (b - ZB - 2 * WB) * 8 + (threadIdx.x >> 5);
    int lane = threadIdx.x & 31;
    if (t >= T) return;

    const float* xr = x + (size_t)t * DM;
    float acc[EM];
#pragma unroll
    for (int e = 0; e < EM; e++) acc[e] = 0.0f;
    for (int d = lane; d < DM; d += 32) {
        float xv = xr[d];
        const float4 w0 = *(const float4*)(Wr + (size_t)d * EM);
        const float4 w1 = *(const float4*)(Wr + (size_t)d * EM + 4);
        acc[0] += xv * w0.x; acc[1] += xv * w0.y;
        acc[2] += xv * w0.z; acc[3] += xv * w0.w;
        acc[4] += xv * w1.x; acc[5] += xv * w1.y;
        acc[6] += xv * w1.z; acc[7] += xv * w1.w;
    }
#pragma unroll
    for (int e = 0; e < EM; e++) {
#pragma unroll
        for (int o = 16; o > 0; o >>= 1)
            acc[e] += __shfl_xor_sync(0xffffffffu, acc[e], o);
    }
    if (lane == 0) {
        float v[EM];
#pragma unroll
        for (int e = 0; e < EM; e++) v[e] = acc[e] + br[e];
        int b0 = 0; float m0 = v[0];
#pragma unroll
        for (int e = 1; e < EM; e++) if (v[e] > m0) { m0 = v[e]; b0 = e; }
        int b1 = -1; float m1 = -3.4e38f;
#pragma unroll
        for (int e = 0; e < EM; e++) {
            if (e == b0) continue;
            if (v[e] > m1) { m1 = v[e]; b1 = e; }
        }
        float p0 = 1.0f / (1.0f + expf(m1 - m0));
        float p1 = 1.0f - p0;
        int pos = atomicAdd(&g_count[b0], 1);
        g_tok[b0 * T + pos] = t;  g_gate[b0 * T + pos] = p0;
        pos = atomicAdd(&g_count[b1], 1);
        g_tok[b1 * T + pos] = t;  g_gate[b1 * T + pos] = p1;
    }
}

// ---------------------------------------------------------------------------
// fp16 gemm step: one BK=32 k-tile, warp tile 64x32.
// HOISTED: all 12 LDSM (both kk-steps) issued before all 32 MMAs.
// ---------------------------------------------------------------------------
__device__ __forceinline__ void gemm_step_f16(
    uint32_t sa_base, uint32_t sb_base,
    int wm, int wn, int lane, float cc[4][4][4]) {

    const int mid = lane >> 3, mr = lane & 7;
    const int arow  = (mid & 1) * 8 + mr;
    const int akoff = (mid >> 1) * 8;
    const int bkrow = (mid & 1) * 8 + mr;
    const int bcoff = (mid >> 1) * 8;

    uint32_t af[2][4][4];
    uint32_t bf[2][4][2];
#pragma unroll
    for (int s = 0; s < 2; s++) {
        const int kk = s * 16;
#pragma unroll
        for (int im = 0; im < 4; im++) {
            uint32_t addr = sa_base + ((wm + im * 16 + arow) * ASTRH + kk + akoff) * 2;
            ldsm4(af[s][im][0], af[s][im][1], af[s][im][2], af[s][im][3], addr);
        }
#pragma unroll
        for (int inp = 0; inp < 2; inp++) {
            uint32_t addr = sb_base + ((kk + bkrow) * BSTRH + wn + inp * 16 + bcoff) * 2;
            uint32_t r0, r1, r2, r3;
            ldsm4t(r0, r1, r2, r3, addr);
            bf[s][2 * inp    ][0] = r0; bf[s][2 * inp    ][1] = r1;
            bf[s][2 * inp + 1][0] = r2; bf[s][2 * inp + 1][1] = r3;
        }
    }
#pragma unroll
    for (int s = 0; s < 2; s++)
#pragma unroll
        for (int in = 0; in < 4; in++)
#pragma unroll
            for (int im = 0; im < 4; im++)
                mma_f16(cc[im][in], af[s][im], bf[s][in]);
}

// wait so that tile kt is complete: pending-beyond-kt = min(2, KT-1-kt)
#define PIPE_WAIT(kt, KT)                              \
    do {                                               \
        if ((KT) - 1 - (kt) >= 2)      cp_wait<2>();   \
        else if ((KT) - 1 - (kt) == 1) cp_wait<1>();   \
        else                           cp_wait<0>();   \
    } while (0)

// ---------------------------------------------------------------------------
// phase 1: h = silu(x@Wg+bg) * (x@Wu+bu), fp16 MMA
// z < EM: GEMM blocks. z == EM: Wd fp32->fp16 conversion (overlapped).
// grid: (T/BM, HM/64, EM+1), 256 threads, 4-stage cp.async, 1 sync/k-tile
// ---------------------------------------------------------------------------
__global__ __launch_bounds__(256, 2) void k_ffn1(
    const float* __restrict__ bg, const float* __restrict__ bu,
    const float4* __restrict__ Wd4) {

    const int tid = threadIdx.x;

    if (blockIdx.z == EM) {
        // convert Wd concurrently with the GEMM (ffn1 never reads Wd)
        int base = (blockIdx.y * gridDim.x + blockIdx.x) * 256 + tid;   // 4096 blocks
        __half2* dst = (__half2*)g_wdh;
#pragma unroll
        for (int r = 0; r < 8; r++) {
            int i = base + r * 1048576;
            float4 v = Wd4[i];
            dst[2 * i    ] = __floats2half2_rn(v.x, v.y);
            dst[2 * i + 1] = __floats2half2_rn(v.z, v.w);
        }
        return;
    }

    const int e      = blockIdx.z;
    const int cnt    = g_count[e];
    const int m_base = blockIdx.x * BM;
    if (m_base >= cnt) return;
    const int n_base = blockIdx.y * 64;   // logical H columns

    extern __shared__ __align__(16) char smem[];
    __half* sA  = (__half*)smem;
    __half* sB  = (__half*)(smem + OFF_SB);
    int*   sTok = (int*)(smem + OFF_TOK);

    const int warp = tid >> 5, lane = tid & 31;
    const int g    = lane >> 2, tq  = lane & 3;
    const int wm   = (warp & 1) * 64;
    const int wn   = (warp >> 1) * 32;

    if (tid < BM) {
        int r = m_base + tid;
        sTok[tid] = (r < cnt) ? g_tok[e * T + r] : 0;
    }
    __syncthreads();

    float cc[4][4][4];
#pragma unroll
    for (int a = 0; a < 4; a++)
#pragma unroll
        for (int b = 0; b < 4; b++)
#pragma unroll
            for (int c = 0; c < 4; c++) cc[a][b][c] = 0.0f;

    const __half* wg = g_wgh + (size_t)e * DM * HM + n_base;
    const __half* wu = g_wuh + (size_t)e * DM * HM + n_base;

    auto load_tiles = [&](int st, int k0) {
#pragma unroll
        for (int j = 0; j < 2; j++) {          // A: 128 rows x 32 halves
            int idx = tid + j * 256;
            int row = idx >> 2;
            int c8  = (idx & 3) << 3;
            cp16(&sA[st * SA_STG + row * ASTRH + c8],
                 g_xh + (size_t)sTok[row] * DM + k0 + c8, true);
        }
#pragma unroll
        for (int j = 0; j < 2; j++) {          // B: 32 rows x 128 halves (16 n8-chunks)
            int idx = tid + j * 256;
            int kr  = idx >> 4;
            int q   = idx & 15;                // even=Wg, odd=Wu
            const __half* src = (q & 1) ? wu : wg;
            cp16(&sB[st * SB_STG + kr * BSTRH + (q << 3)],
                 src + (size_t)(k0 + kr) * HM + ((q >> 1) << 3), true);
        }
        cp_commit();
    };

    uint32_t sa0 = (uint32_t)__cvta_generic_to_shared(sA);
    uint32_t sb0 = (uint32_t)__cvta_generic_to_shared(sB);
    const uint32_t saSz = SA_STG * 2, sbSz = SB_STG * 2;

    load_tiles(0, 0);
    load_tiles(1, BK);
    load_tiles(2, 2 * BK);
    const int KT = DM / BK;   // 32
    for (int kt = 0; kt < KT; kt++) {
        int cur = kt & (NSTG - 1);
        PIPE_WAIT(kt, KT);
        __syncthreads();
        if (kt + 3 < KT) load_tiles((kt + 3) & (NSTG - 1), (kt + 3) * BK);
        gemm_step_f16(sa0 + cur * saSz, sb0 + cur * sbSz, wm, wn, lane, cc);
    }

    // epilogue: in=2j -> gate, in=2j+1 -> up, same logical cols, register silu
    const float* bge = bg + (size_t)e * HM;
    const float* bue = bu + (size_t)e * HM;
    __half* hb = g_hh + (size_t)e * T * HM;
#pragma unroll
    for (int im = 0; im < 4; im++) {
        int r0 = m_base + wm + im * 16 + g;
#pragma unroll
        for (int j = 0; j < 2; j++) {
            int c0 = n_base + ((wn >> 4) + j) * 8 + 2 * tq;
            float bg0 = bge[c0], bg1 = bge[c0 + 1];
            float bu0 = bue[c0], bu1 = bue[c0 + 1];
            if (r0 < cnt) {
                float gv0 = cc[im][2 * j][0] + bg0, gv1 = cc[im][2 * j][1] + bg1;
                float uv0 = cc[im][2 * j + 1][0] + bu0, uv1 = cc[im][2 * j + 1][1] + bu1;
                *(__half2*)(hb + (size_t)r0 * HM + c0) = __floats2half2_rn(
                    gv0 / (1.0f + expf(-gv0)) * uv0,
                    gv1 / (1.0f + expf(-gv1)) * uv1);
            }
            if (r0 + 8 < cnt) {
                float gv0 = cc[im][2 * j][2] + bg0, gv1 = cc[im][2 * j][3] + bg1;
                float uv0 = cc[im][2 * j + 1][2] + bu0, uv1 = cc[im][2 * j + 1][3] + bu1;
                *(__half2*)(hb + (size_t)(r0 + 8) * HM + c0) = __floats2half2_rn(
                    gv0 / (1.0f + expf(-gv0)) * uv0,
                    gv1 / (1.0f + expf(-gv1)) * uv1);
            }
        }
    }
}

// ---------------------------------------------------------------------------
// phase 2: out[tok] += gate * (h @ Wd + bd), fp16 MMA
// grid: (T/BM, DM/128, EM), 256 threads, 4-stage cp.async, 1 sync/k-tile
// ---------------------------------------------------------------------------
__global__ __launch_bounds__(256, 2) void k_ffn2(
    const float* __restrict__ bd, float* __restrict__ out) {

    const int e      = blockIdx.z;
    const int cnt    = g_count[e];
    const int m_base = blockIdx.x * BM;
    if (m_base >= cnt) return;
    const int n_base = blockIdx.y * 128;

    extern __shared__ __align__(16) char smem[];
    __half* sA   = (__half*)smem;
    __half* sB   = (__half*)(smem + OFF_SB);
    int*   sTok  = (int*)(smem + OFF_TOK);
    float* sGate = (float*)(smem + OFF_GATE);

    const int tid  = threadIdx.x;
    const int warp = tid >> 5, lane = tid & 31;
    const int g    = lane >> 2, tq  = lane & 3;
    const int wm   = (warp & 1) * 64;
    const int wn   = (warp >> 1) * 32;

    if (tid < BM) {
        int r = m_base + tid;
        sTok[tid]  = (r < cnt) ? g_tok[e * T + r]  : 0;
        sGate[tid] = (r < cnt) ? g_gate[e * T + r] : 0.0f;
    }

    float cc[4][4][4];
#pragma unroll
    for (int a = 0; a < 4; a++)
#pragma unroll
        for (int b = 0; b < 4; b++)
#pragma unroll
            for (int c = 0; c < 4; c++) cc[a][b][c] = 0.0f;

    const __half* hb = g_hh + (size_t)e * T * HM;
    const __half* wd = g_wdh + (size_t)e * HM * DM + n_base;

    auto load_tiles = [&](int st, int k0) {
#pragma unroll
        for (int j = 0; j < 2; j++) {          // A: 128 slot rows x 32 halves (zfill)
            int idx = tid + j * 256;
            int row = idx >> 2;
            int c8  = (idx & 3) << 3;
            bool v  = (m_base + row) < cnt;
            cp16(&sA[st * SA_STG + row * ASTRH + c8],
                 hb + (size_t)(m_base + row) * HM + k0 + c8, v);
        }
#pragma unroll
        for (int j = 0; j < 2; j++) {          // B: 32 rows x 128 halves
            int idx = tid + j * 256;
            int kr  = idx >> 4;
            int c8  = (idx & 15) << 3;
            cp16(&sB[st * SB_STG + kr * BSTRH + c8],
                 wd + (size_t)(k0 + kr) * DM + c8, true);
        }
        cp_commit();
    };

    uint32_t sa0 = (uint32_t)__cvta_generic_to_shared(sA);
    uint32_t sb0 = (uint32_t)__cvta_generic_to_shared(sB);
    const uint32_t saSz = SA_STG * 2, sbSz = SB_STG * 2;

    load_tiles(0, 0);
    load_tiles(1, BK);
    load_tiles(2, 2 * BK);
    const int KT = HM / BK;   // 128
    for (int kt = 0; kt < KT; kt++) {
        int cur = kt & (NSTG - 1);
        PIPE_WAIT(kt, KT);
        __syncthreads();
        if (kt + 3 < KT) load_tiles((kt + 3) & (NSTG - 1), (kt + 3) * BK);
        gemm_step_f16(sa0 + cur * saSz, sb0 + cur * sbSz, wm, wn, lane, cc);
    }

    // epilogue: gate-weighted scatter atomicAdd
    const float* bde = bd + (size_t)e * DM;
#pragma unroll
    for (int im = 0; im < 4; im++) {
        int rl = wm + im * 16 + g;
        int rg = m_base + rl;
#pragma unroll
        for (int in = 0; in < 4; in++) {
            int n = n_base + wn + in * 8 + tq * 2;
            float b0 = bde[n], b1 = bde[n + 1];
            if (rg < cnt) {
                int   t  = sTok[rl];
                float gt = sGate[rl];
                atomicAdd(&out[(size_t)t * DM + n    ], gt * (cc[im][in][0] + b0));
                atomicAdd(&out[(size_t)t * DM + n + 1], gt * (cc[im][in][1] + b1));
            }
            if (rg + 8 < cnt) {
                int   t  = sTok[rl + 8];
                float gt = sGate[rl + 8];
                atomicAdd(&out[(size_t)t * DM + n    ], gt * (cc[im][in][2] + b0));
                atomicAdd(&out[(size_t)t * DM + n + 1], gt * (cc[im][in][3] + b1));
            }
        }
    }
}

// ---------------------------------------------------------------------------
extern "C" void kernel_launch(void* const* d_in, const int* in_sizes, int n_in,
                              void* d_out, int out_size) {
    const float* x  = (const float*)d_in[0];
    const float* Wr = (const float*)d_in[1];
    const float* br = (const float*)d_in[2];
    const float* Wg = (const float*)d_in[3];
    const float* bg = (const float*)d_in[4];
    const float* Wu = (const float*)d_in[5];
    const float* bu = (const float*)d_in[6];
    const float* Wd = (const float*)d_in[7];
    const float* bd = (const float*)d_in[8];
    float* out = (float*)d_out;

    cudaFuncSetAttribute(k_ffn1, cudaFuncAttributeMaxDynamicSharedMemorySize, SMEM_BYTES);
    cudaFuncSetAttribute(k_ffn2, cudaFuncAttributeMaxDynamicSharedMemorySize, SMEM_BYTES);

    // zero router counters (router atomics live in k_prep_all)
    void* cnt_ptr;
    cudaGetSymbolAddress(&cnt_ptr, g_count);
    cudaMemsetAsync(cnt_ptr, 0, EM * sizeof(int));

    // fused prep: zero out + x cvt + Wg/Wu cvt + router
    k_prep_all<<<ZB + 2 * WB + RB, 256>>>(
        (float4*)out, (const float4*)x, x, Wr, br,
        (const float4*)Wg, (const float4*)Wu);

    // ffn1 GEMM + overlapped Wd conversion (z == EM plane)
    dim3 g1(T / BM, HM / 64, EM + 1);
    k_ffn1<<<g1, 256, SMEM_BYTES>>>(bg, bu, (const float4*)Wd);

    dim3 g2(T / BM, DM / 128, EM);
    k_ffn2<<<g2, 256, SMEM_BYTES>>>(bd, out);
}